// round 12
// baseline (speedup 1.0000x reference)
#include <cuda_runtime.h>
#include <cuda_bf16.h>
#include <math.h>

#define B_    2
#define S_    2048
#define HID_  2048
#define NH_   16
#define NKV_  8
#define D_    128
#define G_    (NH_/NKV_)
#define BSR_  (B_*S_)          // 4096

// -------- scratch (__device__ globals; no allocations) --------
// flash operands, mma-fragment-packed bf16 hi/lo
__device__ unsigned g_Qph[BSR_ * NH_ * D_ / 2];     // [rowblk32*NH_][kk8][wr8][ln32] uint4
__device__ unsigned g_Qpl[BSR_ * NH_ * D_ / 2];
__device__ unsigned g_Kph[BSR_ * NKV_ * D_ / 2];    // [b2][kvh8][kt32][kk8][np4][ln32] uint4
__device__ unsigned g_Kpl[BSR_ * NKV_ * D_ / 2];
__device__ unsigned g_Vph[BSR_ * NKV_ * D_ / 2];    // [b2][kvh8][kt32][kk2 4][np8][ln32] uint4
__device__ unsigned g_Vpl[BSR_ * NKV_ * D_ / 2];
// GEMM operands, fragment-packed tf32
__device__ unsigned g_Xp [BSR_ * HID_];
__device__ unsigned g_Ctp[BSR_ * NH_ * D_];
__device__ unsigned g_Wqp[HID_ * NH_ * D_];
__device__ unsigned g_Wkp[HID_ * NKV_ * D_];
__device__ unsigned g_Wvp[HID_ * NKV_ * D_];
__device__ unsigned g_Wop[NH_ * D_ * HID_];
__device__ float g_cos[S_ * 64];
__device__ float g_sin[S_ * 64];

// ---------------- helpers ----------------
__device__ __forceinline__ unsigned f2tf(float x) {
    unsigned u;
    asm("cvt.rna.tf32.f32 %0, %1;" : "=r"(u) : "f"(x));
    return u;
}
__device__ __forceinline__ void cp16(unsigned dst, const void* src) {
    asm volatile("cp.async.cg.shared.global [%0], [%1], 16;" :: "r"(dst), "l"(src));
}
__device__ __forceinline__ void cp_commit() { asm volatile("cp.async.commit_group;"); }
__device__ __forceinline__ void cp_wait1()  { asm volatile("cp.async.wait_group 1;"); }
__device__ __forceinline__ void cp_wait0()  { asm volatile("cp.async.wait_group 0;"); }

__device__ __forceinline__ void split2(float x, float y, unsigned& hi, unsigned& lo) {
    __nv_bfloat16 hx = __float2bfloat16_rn(x);
    __nv_bfloat16 hy = __float2bfloat16_rn(y);
    float rx = x - __bfloat162float(hx);
    float ry = y - __bfloat162float(hy);
    __nv_bfloat162 h; h.x = hx; h.y = hy;
    __nv_bfloat162 l; l.x = __float2bfloat16_rn(rx); l.y = __float2bfloat16_rn(ry);
    hi = *(unsigned*)&h;
    lo = *(unsigned*)&l;
}

__device__ __forceinline__ void mma_tf32(float* d, const unsigned* a, const unsigned* b) {
    asm volatile(
        "mma.sync.aligned.m16n8k8.row.col.f32.tf32.tf32.f32 "
        "{%0,%1,%2,%3}, {%4,%5,%6,%7}, {%8,%9}, {%0,%1,%2,%3};\n"
        : "+f"(d[0]), "+f"(d[1]), "+f"(d[2]), "+f"(d[3])
        : "r"(a[0]), "r"(a[1]), "r"(a[2]), "r"(a[3]), "r"(b[0]), "r"(b[1]));
}
__device__ __forceinline__ void mma_bf16(float* d, const unsigned* a, const unsigned* b) {
    asm volatile(
        "mma.sync.aligned.m16n8k16.row.col.f32.bf16.bf16.f32 "
        "{%0,%1,%2,%3}, {%4,%5,%6,%7}, {%8,%9}, {%0,%1,%2,%3};\n"
        : "+f"(d[0]), "+f"(d[1]), "+f"(d[2]), "+f"(d[3])
        : "r"(a[0]), "r"(a[1]), "r"(a[2]), "r"(a[3]), "r"(b[0]), "r"(b[1]));
}

__device__ __forceinline__ float rope_elem(const float* sf, int r, int s, int c) {
    if (c < 64)
        return sf[r * 132 + c] * g_cos[s * 64 + c] - sf[r * 132 + c + 64] * g_sin[s * 64 + c];
    int i = c - 64;
    return sf[r * 132 + c] * g_cos[s * 64 + i] + sf[r * 132 + c - 64] * g_sin[s * 64 + i];
}

// ============================================================
// Fused packing of all GEMM operands (layouts validated).
// ============================================================
__device__ __forceinline__ void pack_a_one(
    const float* __restrict__ A, unsigned* __restrict__ P, int id)
{
    int w      = id & 1023;
    int chunk  = id >> 10;
    int kchunk = chunk & 63;
    int mtile  = chunk >> 6;
    int lane = w & 31, rf = (w >> 5) & 7, kk = w >> 8;
    int row = mtile * 128 + rf * 16 + (lane >> 2);
    int col = kchunk * 32 + kk * 8 + (lane & 3);
    const float* a0 = A + (size_t)row * HID_ + col;
    ((uint4*)P)[id] = make_uint4(
        f2tf(a0[0]), f2tf(a0[8 * HID_]), f2tf(a0[4]), f2tf(a0[8 * HID_ + 4]));
}

__device__ __forceinline__ void pack_b_one(
    const float* __restrict__ W, unsigned* __restrict__ P, int N, int id)
{
    int w      = id & 2047;
    int chunk  = id >> 11;
    int kchunk = chunk & 63;
    int ntile  = chunk >> 6;
    int lane = w & 31, nb = (w >> 5) & 15, kk = w >> 9;
    int n = ntile * 128 + nb * 8 + (lane >> 2);
    int c = kchunk * 32 + kk * 8 + (lane & 3);
    ((uint2*)P)[id] = make_uint2(
        f2tf(W[(size_t)c * N + n]), f2tf(W[(size_t)(c + 4) * N + n]));
}

__global__ void pack_all(const float* __restrict__ X,
                         const float* __restrict__ Wq, const float* __restrict__ Wk,
                         const float* __restrict__ Wv, const float* __restrict__ Wo)
{
    const int NA = (BSR_ * HID_) / 4;
    const int NQ = (2048 * HID_) / 2;
    const int NK = (1024 * HID_) / 2;
    int id = blockIdx.x * blockDim.x + threadIdx.x;
    if (id < NA) { pack_a_one(X, g_Xp, id); return; }
    id -= NA;
    if (id < NQ)              { pack_b_one(Wq, g_Wqp, 2048, id); return; }
    if (id < NQ + NK)         { pack_b_one(Wk, g_Wkp, 1024, id - NQ); return; }
    if (id < NQ + 2 * NK)     { pack_b_one(Wv, g_Wvp, 1024, id - NQ - NK); return; }
    if (id < NQ + 2 * NK + NQ)  pack_b_one(Wo, g_Wop, 2048, id - NQ - 2 * NK);
}

// ============================================================
// RoPE tables
// ============================================================
__global__ void rope_table_kernel()
{
    int idx = blockIdx.x * blockDim.x + threadIdx.x;
    if (idx >= S_ * 64) return;
    int s = idx >> 6, i = idx & 63;
    const double NEG_LOG_STEP = -0.2158673524681918;
    double freq = exp((double)i * NEG_LOG_STEP);
    double sd, cd;
    sincos((double)s * freq, &sd, &cd);
    g_cos[idx] = (float)cd;
    g_sin[idx] = (float)sd;
}

// ============================================================
// TF32 GEMM core (validated): 3-stage cp.async, one barrier/chunk.
// ============================================================
#define CHUNK_BYTES 16384
#define STAGE_BYTES (2 * CHUNK_BYTES)
#define GEMM_SMEM   (3 * STAGE_BYTES)          // 98304

__device__ __forceinline__ void gemm_issue_v3(
    unsigned sbase, int stage, const unsigned* __restrict__ Ac,
    const unsigned* __restrict__ Bc, int tid)
{
    unsigned st = sbase + stage * STAGE_BYTES;
#pragma unroll
    for (int p = 0; p < 4; p++) {
        int id = tid + p * 256;
        cp16(st + id * 16,               Ac + id * 4);
        cp16(st + CHUNK_BYTES + id * 16, Bc + id * 4);
    }
    cp_commit();
}

__device__ __forceinline__ void gemm_compute_v3(
    const char* st, float acc[4][4][4], int lane, int wm, int wn)
{
    const char* sA = st;
    const char* sB = st + CHUNK_BYTES;
#pragma unroll
    for (int kk = 0; kk < 4; kk++) {
        uint4 a[4]; uint2 b[4];
#pragma unroll
        for (int mf = 0; mf < 4; mf++)
            a[mf] = *(const uint4*)(sA + (((kk * 8 + wm * 4 + mf) * 32) + lane) * 16);
#pragma unroll
        for (int nf = 0; nf < 4; nf++)
            b[nf] = *(const uint2*)(sB + (((kk * 16 + wn * 4 + nf) * 32) + lane) * 8);
#pragma unroll
        for (int mf = 0; mf < 4; mf++)
#pragma unroll
            for (int nf = 0; nf < 4; nf++)
                mma_tf32(acc[mf][nf], (const unsigned*)&a[mf], (const unsigned*)&b[nf]);
    }
}

__device__ __forceinline__ void gemm_main_v4(
    const unsigned* __restrict__ Ab, const unsigned* __restrict__ Bb,
    float acc[4][4][4], char* smem)
{
    const int tid  = threadIdx.x;
    const int lane = tid & 31;
    const int wm   = (tid >> 5) >> 2;
    const int wn   = (tid >> 5) & 3;
    unsigned sbase = (unsigned)__cvta_generic_to_shared(smem);

    gemm_issue_v3(sbase, 0, Ab, Bb, tid);
    gemm_issue_v3(sbase, 1, Ab + 4096, Bb + 4096, tid);

    for (int i = 0; i < 64; i++) {
        if (i < 63) cp_wait1(); else cp_wait0();
        __syncthreads();
        if (i + 2 < 64)
            gemm_issue_v3(sbase, (i + 2) % 3,
                          Ab + (size_t)(i + 2) * 4096,
                          Bb + (size_t)(i + 2) * 4096, tid);
        gemm_compute_v3(smem + (i % 3) * STAGE_BYTES, acc, lane, wm, wn);
    }
}

// ============================================================
// Fused QKV projections; epilogues emit flash-fragment-packed
// Q (A-frag) and K/V (PAIRED B-frags, uint4 per two nf).
// 1024 blocks: 512 Q, 256 K, 256 V.
// ============================================================
__global__ __launch_bounds__(256, 2) void gemm_qkv(
    const unsigned* __restrict__ Ap,
    const float* __restrict__ bq, const float* __restrict__ bk,
    const float* __restrict__ bv)
{
    extern __shared__ char smem[];
    float* sf = (float*)smem;
    const int id = blockIdx.x;
    const unsigned* Bp; const float* bias;
    int bx, by, mode;
    if (id < 512)      { Bp = g_Wqp; bias = bq; bx = id & 15; by = id >> 4; mode = 0; }
    else if (id < 768) { int t = id - 512; Bp = g_Wkp; bias = bk; bx = t & 7; by = t >> 3; mode = 1; }
    else               { int t = id - 768; Bp = g_Wvp; bias = bv; bx = t & 7; by = t >> 3; mode = 2; }

    float acc[4][4][4];
#pragma unroll
    for (int i = 0; i < 4; i++)
#pragma unroll
        for (int j = 0; j < 4; j++)
#pragma unroll
            for (int e = 0; e < 4; e++) acc[i][j][e] = 0.0f;

    gemm_main_v4(Ap + (size_t)by * 64 * 4096, Bp + (size_t)bx * 64 * 4096, acc, smem);
    __syncthreads();

    const int tid  = threadIdx.x;
    const int lane = tid & 31;
    const int warp = tid >> 5;
    const int wm = warp >> 2, wn = warp & 3;

    // ---- stage tile (Q/K row-major [r][132]; V transposed [d][132]) ----
#pragma unroll
    for (int mf = 0; mf < 4; mf++) {
        int r = wm * 64 + mf * 16 + (lane >> 2);
#pragma unroll
        for (int nf = 0; nf < 4; nf++) {
            int col = wn * 32 + nf * 8 + 2 * (lane & 3);
            float b0 = bias[bx * 128 + col], b1 = bias[bx * 128 + col + 1];
            float v00 = acc[mf][nf][0] + b0, v01 = acc[mf][nf][1] + b1;
            float v10 = acc[mf][nf][2] + b0, v11 = acc[mf][nf][3] + b1;
            if (mode != 2) {
                *(float2*)(sf + r * 132 + col)       = make_float2(v00, v01);
                *(float2*)(sf + (r + 8) * 132 + col) = make_float2(v10, v11);
            } else {
                sf[col * 132 + r]           = v00;
                sf[(col + 1) * 132 + r]     = v01;
                sf[col * 132 + r + 8]       = v10;
                sf[(col + 1) * 132 + r + 8] = v11;
            }
        }
    }
    __syncthreads();

    if (mode == 0) {
        // ---- Q: rope + split, A-frag packed per (rowblk by, head bx) ----
        unsigned* Qh = g_Qph + (size_t)(by * 16 + bx) * 8192;
        unsigned* Ql = g_Qpl + (size_t)(by * 16 + bx) * 8192;
        for (int it = tid; it < 2048; it += 256) {
            int kk = it >> 8, wr = (it >> 5) & 7, ln = it & 31;
            int r = wr * 16 + (ln >> 2);
            int c = kk * 16 + 2 * (ln & 3);
            int s  = (by * 128 + r) & (S_ - 1);
            int s8 = s + 8;
            float e0 = rope_elem(sf, r, s, c);
            float e1 = rope_elem(sf, r, s, c + 1);
            float e2 = rope_elem(sf, r + 8, s8, c);
            float e3 = rope_elem(sf, r + 8, s8, c + 1);
            float e4 = rope_elem(sf, r, s, c + 8);
            float e5 = rope_elem(sf, r, s, c + 9);
            float e6 = rope_elem(sf, r + 8, s8, c + 8);
            float e7 = rope_elem(sf, r + 8, s8, c + 9);
            unsigned h0,l0,h1,l1,h2,l2,h3,l3;
            split2(e0, e1, h0, l0); split2(e2, e3, h1, l1);
            split2(e4, e5, h2, l2); split2(e6, e7, h3, l3);
            ((uint4*)Qh)[it] = make_uint4(h0, h1, h2, h3);
            ((uint4*)Ql)[it] = make_uint4(l0, l1, l2, l3);
        }
    } else if (mode == 1) {
        // ---- K: rope + split, PAIRED B-frags: [kt][kk8][np4][ln32] uint4 ----
        const int bb  = (by * 128) >> 11;
        const int kt0 = ((by * 128) & (S_ - 1)) >> 6;
        size_t kbase4 = ((size_t)((bb * NKV_ + bx) * 32 + kt0)) * 1024;   // uint4 units
        for (int it = tid; it < 2048; it += 256) {
            int kt = it >> 10, w = it & 1023;
            int kk = w >> 7, np = (w >> 5) & 3, ln = w & 31;
            int c = kk * 16 + 2 * (ln & 3);
            unsigned hv[4], lv[4];
#pragma unroll
            for (int p = 0; p < 2; p++) {
                int n = (2 * np + p) * 8 + (ln >> 2);
                int r = kt * 64 + n;
                int s = (by * 128 + r) & (S_ - 1);
                float e0 = rope_elem(sf, r, s, c);
                float e1 = rope_elem(sf, r, s, c + 1);
                float e2 = rope_elem(sf, r, s, c + 8);
                float e3 = rope_elem(sf, r, s, c + 9);
                split2(e0, e1, hv[2*p],   lv[2*p]);
                split2(e2, e3, hv[2*p+1], lv[2*p+1]);
            }
            ((uint4*)g_Kph)[kbase4 + kt * 1024 + w] = make_uint4(hv[0], hv[1], hv[2], hv[3]);
            ((uint4*)g_Kpl)[kbase4 + kt * 1024 + w] = make_uint4(lv[0], lv[1], lv[2], lv[3]);
        }
    } else {
        // ---- V: split, PAIRED transposed B-frags: [kt][kk2 4][np8][ln32] uint4 ----
        const int bb  = (by * 128) >> 11;
        const int kt0 = ((by * 128) & (S_ - 1)) >> 6;
        size_t vbase4 = ((size_t)((bb * NKV_ + bx) * 32 + kt0)) * 1024;
        for (int it = tid; it < 2048; it += 256) {
            int kt = it >> 10, w = it & 1023;
            int kk2 = w >> 8, np = (w >> 5) & 7, ln = w & 31;
            int cl = kk2 * 16 + 2 * (ln & 3);
            int r  = kt * 64 + cl;
            unsigned hv[4], lv[4];
#pragma unroll
            for (int p = 0; p < 2; p++) {
                int n = (2 * np + p) * 8 + (ln >> 2);
                float e0 = sf[n * 132 + r],     e1 = sf[n * 132 + r + 1];
                float e2 = sf[n * 132 + r + 8], e3 = sf[n * 132 + r + 9];
                split2(e0, e1, hv[2*p],   lv[2*p]);
                split2(e2, e3, hv[2*p+1], lv[2*p+1]);
            }
            ((uint4*)g_Vph)[vbase4 + kt * 1024 + w] = make_uint4(hv[0], hv[1], hv[2], hv[3]);
            ((uint4*)g_Vpl)[vbase4 + kt * 1024 + w] = make_uint4(lv[0], lv[1], lv[2], lv[3]);
        }
    }
}

// ============================================================
// O projection GEMM (unchanged)
// ============================================================
__global__ __launch_bounds__(256, 2) void gemm_v3(
    const unsigned* __restrict__ Ap, const unsigned* __restrict__ Bp,
    float* __restrict__ C, int N)
{
    extern __shared__ char smem[];
    float acc[4][4][4];
#pragma unroll
    for (int i = 0; i < 4; i++)
#pragma unroll
        for (int j = 0; j < 4; j++)
#pragma unroll
            for (int e = 0; e < 4; e++) acc[i][j][e] = 0.0f;

    gemm_main_v4(Ap + (size_t)blockIdx.y * 64 * 4096,
                 Bp + (size_t)blockIdx.x * 64 * 4096, acc, smem);

    const int lane = threadIdx.x & 31;
    const int warp = threadIdx.x >> 5;
    const int wm = warp >> 2, wn = warp & 3;
#pragma unroll
    for (int mf = 0; mf < 4; mf++) {
        int row = blockIdx.y * 128 + wm * 64 + mf * 16 + (lane >> 2);
#pragma unroll
        for (int nf = 0; nf < 4; nf++) {
            int col = blockIdx.x * 128 + wn * 32 + nf * 8 + 2 * (lane & 3);
            *(float2*)&C[(size_t)row * N + col] =
                make_float2(acc[mf][nf][0], acc[mf][nf][1]);
            *(float2*)&C[(size_t)(row + 8) * N + col] =
                make_float2(acc[mf][nf][2], acc[mf][nf][3]);
        }
    }
}

// ============================================================
// Flash attention (R10 structure, BQ=128): paired-fragment K/V,
// all LDS.128, register softmax/P, ctx A-pack epilogue.
// smem: QH 32K | QL 32K | 2 stages x (Kh16K Kl16K Vh16K Vl16K)
// ============================================================
#define BQ 128
#define QH_OFF 0
#define QL_OFF 32768
#define ST0_OFF 65536
#define FSTAGE 65536
#define FLASH_SMEM (ST0_OFF + 2 * FSTAGE)     // 196608

__device__ __forceinline__ void flash_issue(
    unsigned sbase, int stage, size_t base_u, int tid)
{
    unsigned st = sbase + ST0_OFF + stage * FSTAGE;
#pragma unroll
    for (int p = 0; p < 4; p++) {
        int id = tid + p * 256;                 // 0..1023
        cp16(st + id * 16,         g_Kph + base_u + id * 4);
        cp16(st + 16384 + id * 16, g_Kpl + base_u + id * 4);
        cp16(st + 32768 + id * 16, g_Vph + base_u + id * 4);
        cp16(st + 49152 + id * 16, g_Vpl + base_u + id * 4);
    }
    cp_commit();
}

__global__ __launch_bounds__(256, 1) void flash_bf16()
{
    extern __shared__ char sm[];
    const int tid  = threadIdx.x;
    const int lane = tid & 31;
    const int warp = tid >> 5;
    const int qtile = (gridDim.x - 1) - blockIdx.x;
    const int h    = blockIdx.y;
    const int b    = blockIdx.z;
    const int kvh  = h / G_;
    const int qbase = qtile * BQ;
    const float scale = 0.08838834764831845f;
    const int g = lane >> 2;
    const int t = lane & 3;
    const int m0 = warp * 16;
    unsigned sbase = (unsigned)__cvta_generic_to_shared(sm);

    const size_t kvstep = 4096;                       // unsigned per 64-key tile
    const size_t kvb0 = ((size_t)(b * NKV_ + kvh) * 32) * kvstep;

    flash_issue(sbase, 0, kvb0, tid);

    // Q tile: linear copy of packed fragments
    {
        const int mq = (b * S_ + qbase) >> 7;
        const uint4* qh = (const uint4*)g_Qph + (size_t)(mq * 16 + h) * 2048;
        const uint4* ql = (const uint4*)g_Qpl + (size_t)(mq * 16 + h) * 2048;
        for (int it = tid; it < 2048; it += 256) {
            *(uint4*)(sm + QH_OFF + it * 16) = qh[it];
            *(uint4*)(sm + QL_OFF + it * 16) = ql[it];
        }
    }

    float ctx[16][4];
#pragma unroll
    for (int i = 0; i < 16; i++)
#pragma unroll
        for (int e = 0; e < 4; e++) ctx[i][e] = 0.0f;
    float mr0 = -INFINITY, mr1 = -INFINITY, lr0 = 0.0f, lr1 = 0.0f;

    const int row0 = qbase + m0 + g;
    const int row1 = row0 + 8;
    const int ntile = 2 * qtile + 2;

    for (int j = 0; j < ntile; j++) {
        const int kb = j * 64;
        if (j + 1 < ntile) {
            flash_issue(sbase, (j + 1) & 1, kvb0 + (size_t)(j + 1) * kvstep, tid);
            cp_wait1();
        } else {
            cp_wait0();
        }
        __syncthreads();

        const char* stg  = sm + ST0_OFF + (j & 1) * FSTAGE;
        const char* stK  = stg;
        const char* stKL = stg + 16384;
        const char* stV  = stg + 32768;
        const char* stVL = stg + 49152;

        float acc[8][4];
#pragma unroll
        for (int nf = 0; nf < 8; nf++)
#pragma unroll
            for (int e = 0; e < 4; e++) acc[nf][e] = 0.0f;

#pragma unroll
        for (int kk = 0; kk < 8; kk++) {
            uint4 aH = *(const uint4*)(sm + QH_OFF + (kk * 256 + warp * 32 + lane) * 16);
            uint4 aL = *(const uint4*)(sm + QL_OFF + (kk * 256 + warp * 32 + lane) * 16);
#pragma unroll
            for (int np = 0; np < 4; np++) {
                uint4 bH2 = *(const uint4*)(stK  + (kk * 128 + np * 32 + lane) * 16);
                uint4 bL2 = *(const uint4*)(stKL + (kk * 128 + np * 32 + lane) * 16);
                const unsigned* bh = (const unsigned*)&bH2;
                const unsigned* bl = (const unsigned*)&bL2;
                mma_bf16(acc[2*np],     (const unsigned*)&aH, bh);
                mma_bf16(acc[2*np],     (const unsigned*)&aH, bl);
                mma_bf16(acc[2*np],     (const unsigned*)&aL, bh);
                mma_bf16(acc[2*np + 1], (const unsigned*)&aH, bh + 2);
                mma_bf16(acc[2*np + 1], (const unsigned*)&aH, bl + 2);
                mma_bf16(acc[2*np + 1], (const unsigned*)&aL, bh + 2);
            }
        }

#pragma unroll
        for (int nf = 0; nf < 8; nf++)
#pragma unroll
            for (int e = 0; e < 4; e++) acc[nf][e] *= scale;

        if (kb + 63 > qbase + m0) {
#pragma unroll
            for (int nf = 0; nf < 8; nf++) {
                int k0 = kb + nf * 8 + 2 * t;
                if (k0     > row0) acc[nf][0] = -INFINITY;
                if (k0 + 1 > row0) acc[nf][1] = -INFINITY;
                if (k0     > row1) acc[nf][2] = -INFINITY;
                if (k0 + 1 > row1) acc[nf][3] = -INFINITY;
            }
        }

        float mx0 = -INFINITY, mx1 = -INFINITY;
#pragma unroll
        for (int nf = 0; nf < 8; nf++) {
            mx0 = fmaxf(mx0, fmaxf(acc[nf][0], acc[nf][1]));
            mx1 = fmaxf(mx1, fmaxf(acc[nf][2], acc[nf][3]));
        }
        mx0 = fmaxf(mx0, __shfl_xor_sync(0xffffffffu, mx0, 1));
        mx0 = fmaxf(mx0, __shfl_xor_sync(0xffffffffu, mx0, 2));
        mx1 = fmaxf(mx1, __shfl_xor_sync(0xffffffffu, mx1, 1));
        mx1 = fmaxf(mx1, __shfl_xor_sync(0xffffffffu, mx1, 2));

        float mn0 = fmaxf(mr0, mx0);
        float mn1 = fmaxf(mr1, mx1);
        float al0 = __expf(mr0 - mn0);
        float al1 = __expf(mr1 - mn1);
        mr0 = mn0; mr1 = mn1;

        unsigned pH[4][4], pL[4][4];
        float s0 = 0.0f, s1 = 0.0f;
#pragma unroll
        for (int nf = 0; nf < 8; nf++) {
            float p00 = __expf(acc[nf][0] - mn0);
            float p01 = __expf(acc[nf][1] - mn0);
            float p10 = __expf(acc[nf][2] - mn1);
            float p11 = __expf(acc[nf][3] - mn1);
            s0 += p00 + p01;
            s1 += p10 + p11;
            int kk2 = nf >> 1;
            int sl  = (nf & 1) << 1;
            split2(p00, p01, pH[kk2][sl],     pL[kk2][sl]);
            split2(p10, p11, pH[kk2][sl + 1], pL[kk2][sl + 1]);
        }
        s0 += __shfl_xor_sync(0xffffffffu, s0, 1);
        s0 += __shfl_xor_sync(0xffffffffu, s0, 2);
        s1 += __shfl_xor_sync(0xffffffffu, s1, 1);
        s1 += __shfl_xor_sync(0xffffffffu, s1, 2);
        lr0 = lr0 * al0 + s0;
        lr1 = lr1 * al1 + s1;

#pragma unroll
        for (int nf = 0; nf < 16; nf++) {
            ctx[nf][0] *= al0; ctx[nf][1] *= al0;
            ctx[nf][2] *= al1; ctx[nf][3] *= al1;
        }
#pragma unroll
        for (int kk2 = 0; kk2 < 4; kk2++) {
#pragma unroll
            for (int np = 0; np < 8; np++) {
                uint4 vH2 = *(const uint4*)(stV  + (kk2 * 256 + np * 32 + lane) * 16);
                uint4 vL2 = *(const uint4*)(stVL + (kk2 * 256 + np * 32 + lane) * 16);
                const unsigned* vh = (const unsigned*)&vH2;
                const unsigned* vl = (const unsigned*)&vL2;
                mma_bf16(ctx[2*np],     pH[kk2], vh);
                mma_bf16(ctx[2*np],     pL[kk2], vh);
                mma_bf16(ctx[2*np],     pH[kk2], vl);
                mma_bf16(ctx[2*np + 1], pH[kk2], vh + 2);
                mma_bf16(ctx[2*np + 1], pL[kk2], vh + 2);
                mma_bf16(ctx[2*np + 1], pH[kk2], vl + 2);
            }
        }
        __syncthreads();
    }

    // ---- fused epilogue: stage ctx f32, emit A-packed tf32 g_Ctp ----
    float* cs = (float*)(sm + ST0_OFF);        // 128x132 f32
    {
        float il0 = 1.0f / lr0;
        float il1 = 1.0f / lr1;
        int rl0 = m0 + g;
#pragma unroll
        for (int nf = 0; nf < 16; nf++) {
            int d = nf * 8 + 2 * t;
            *(float2*)(cs + rl0 * 132 + d) =
                make_float2(ctx[nf][0] * il0, ctx[nf][1] * il0);
            *(float2*)(cs + (rl0 + 8) * 132 + d) =
                make_float2(ctx[nf][2] * il1, ctx[nf][3] * il1);
        }
    }
    __syncthreads();

    {
        const int mtile = (b * S_ + qbase) >> 7;
        for (int it = tid; it < 4096; it += 256) {
            int ln = it & 31, rf = (it >> 5) & 7, kk = (it >> 8) & 3, kc = it >> 10;
            int rl = rf * 16 + (ln >> 2);
            int cl = kc * 32 + kk * 8 + (ln & 3);
            uint4 o = make_uint4(
                f2tf(cs[rl * 132 + cl]),       f2tf(cs[(rl + 8) * 132 + cl]),
                f2tf(cs[rl * 132 + cl + 4]),   f2tf(cs[(rl + 8) * 132 + cl + 4]));
            size_t idx = ((size_t)(mtile * 64 + h * 4 + kc) << 10) +
                         (kk << 8) + (rf << 5) + ln;
            ((uint4*)g_Ctp)[idx] = o;
        }
    }
}

// ============================================================
// launch
// ============================================================
extern "C" void kernel_launch(void* const* d_in, const int* in_sizes, int n_in,
                              void* d_out, int out_size)
{
    (void)in_sizes; (void)n_in; (void)out_size;
    const float* hidden = (const float*)d_in[0];
    const float* Wq = (const float*)d_in[1];
    const float* bq = (const float*)d_in[2];
    const float* Wk = (const float*)d_in[3];
    const float* bk = (const float*)d_in[4];
    const float* Wv = (const float*)d_in[5];
    const float* bv = (const float*)d_in[6];
    const float* Wo = (const float*)d_in[7];
    float* out = (float*)d_out;

    unsigned *xp, *ctp, *wop;
    cudaGetSymbolAddress((void**)&xp,  g_Xp);
    cudaGetSymbolAddress((void**)&ctp, g_Ctp);
    cudaGetSymbolAddress((void**)&wop, g_Wop);

    cudaFuncSetAttribute(gemm_qkv,
        cudaFuncAttributeMaxDynamicSharedMemorySize, GEMM_SMEM);
    cudaFuncSetAttribute(gemm_v3,
        cudaFuncAttributeMaxDynamicSharedMemorySize, GEMM_SMEM);
    cudaFuncSetAttribute(flash_bf16,
        cudaFuncAttributeMaxDynamicSharedMemorySize, FLASH_SMEM);

    const int NPACK = BSR_ * HID_ / 4 + (2048 + 1024 + 1024 + 2048) * HID_ / 2;

    // 1: pack GEMM operands
    pack_all<<<(NPACK + 255) / 256, 256>>>(hidden, Wq, Wk, Wv, Wo);
    // 2: RoPE tables
    rope_table_kernel<<<(S_ * 64 + 255) / 256, 256>>>();
    // 3: fused QKV projections + paired-fragment epilogues
    gemm_qkv<<<1024, 256, GEMM_SMEM>>>(xp, bq, bk, bv);
    // 4: flash attention  ← profiled launch
    flash_bf16<<<dim3(S_ / BQ, NH_, B_), 256, FLASH_SMEM>>>();
    // 5: O projection → final output
    gemm_v3<<<dim3(16, 32), 256, GEMM_SMEM>>>(ctp, wop, out, HID_);
}

// round 13
// speedup vs baseline: 1.0965x; 1.0965x over previous
#include <cuda_runtime.h>
#include <cuda_bf16.h>
#include <cuda_fp16.h>
#include <math.h>

#define B_    2
#define S_    2048
#define HID_  2048
#define NH_   16
#define NKV_  8
#define D_    128
#define G_    (NH_/NKV_)
#define BSR_  (B_*S_)          // 4096

// -------- scratch (__device__ globals; no allocations) --------
// flash operands, mma-fragment-packed fp16 (Q/P hi-only; K/V hi+lo)
__device__ unsigned g_Qph[BSR_ * NH_ * D_ / 2];     // [rowblk32*NH_][kk8][wr8][ln32] uint4
__device__ unsigned g_Kph[BSR_ * NKV_ * D_ / 2];    // [b2][kvh8][kt32][kk8][np4][ln32] uint4
__device__ unsigned g_Kpl[BSR_ * NKV_ * D_ / 2];
__device__ unsigned g_Vph[BSR_ * NKV_ * D_ / 2];    // [b2][kvh8][kt32][kk2 4][np8][ln32] uint4
__device__ unsigned g_Vpl[BSR_ * NKV_ * D_ / 2];
// GEMM operands, fragment-packed tf32 (validated layouts)
__device__ unsigned g_Xp [BSR_ * HID_];
__device__ unsigned g_Ctp[BSR_ * NH_ * D_];
__device__ unsigned g_Wqp[HID_ * NH_ * D_];
__device__ unsigned g_Wkp[HID_ * NKV_ * D_];
__device__ unsigned g_Wvp[HID_ * NKV_ * D_];
__device__ unsigned g_Wop[NH_ * D_ * HID_];
__device__ float g_cos[S_ * 64];
__device__ float g_sin[S_ * 64];

// ---------------- helpers ----------------
__device__ __forceinline__ unsigned f2tf(float x) {
    unsigned u;
    asm("cvt.rna.tf32.f32 %0, %1;" : "=r"(u) : "f"(x));
    return u;
}
__device__ __forceinline__ void cp16(unsigned dst, const void* src) {
    asm volatile("cp.async.cg.shared.global [%0], [%1], 16;" :: "r"(dst), "l"(src));
}
__device__ __forceinline__ void cp_commit() { asm volatile("cp.async.commit_group;"); }
__device__ __forceinline__ void cp_wait1()  { asm volatile("cp.async.wait_group 1;"); }
__device__ __forceinline__ void cp_wait0()  { asm volatile("cp.async.wait_group 0;"); }

// fp16 pack / split
__device__ __forceinline__ unsigned pack_h2(float x, float y) {
    __half2 h;
    h.x = __float2half_rn(x);
    h.y = __float2half_rn(y);
    return *(unsigned*)&h;
}
__device__ __forceinline__ void split2h(float x, float y, unsigned& hi, unsigned& lo) {
    __half hx = __float2half_rn(x);
    __half hy = __float2half_rn(y);
    float rx = x - __half2float(hx);
    float ry = y - __half2float(hy);
    __half2 h; h.x = hx; h.y = hy;
    __half2 l; l.x = __float2half_rn(rx); l.y = __float2half_rn(ry);
    hi = *(unsigned*)&h;
    lo = *(unsigned*)&l;
}

__device__ __forceinline__ void mma_tf32(float* d, const unsigned* a, const unsigned* b) {
    asm volatile(
        "mma.sync.aligned.m16n8k8.row.col.f32.tf32.tf32.f32 "
        "{%0,%1,%2,%3}, {%4,%5,%6,%7}, {%8,%9}, {%0,%1,%2,%3};\n"
        : "+f"(d[0]), "+f"(d[1]), "+f"(d[2]), "+f"(d[3])
        : "r"(a[0]), "r"(a[1]), "r"(a[2]), "r"(a[3]), "r"(b[0]), "r"(b[1]));
}
__device__ __forceinline__ void mma_f16(float* d, const unsigned* a, const unsigned* b) {
    asm volatile(
        "mma.sync.aligned.m16n8k16.row.col.f32.f16.f16.f32 "
        "{%0,%1,%2,%3}, {%4,%5,%6,%7}, {%8,%9}, {%0,%1,%2,%3};\n"
        : "+f"(d[0]), "+f"(d[1]), "+f"(d[2]), "+f"(d[3])
        : "r"(a[0]), "r"(a[1]), "r"(a[2]), "r"(a[3]), "r"(b[0]), "r"(b[1]));
}

__device__ __forceinline__ float rope_elem(const float* sf, int r, int s, int c) {
    if (c < 64)
        return sf[r * 132 + c] * g_cos[s * 64 + c] - sf[r * 132 + c + 64] * g_sin[s * 64 + c];
    int i = c - 64;
    return sf[r * 132 + c] * g_cos[s * 64 + i] + sf[r * 132 + c - 64] * g_sin[s * 64 + i];
}

// ============================================================
// Fused packing of all GEMM operands (validated layouts).
// ============================================================
__device__ __forceinline__ void pack_a_one(
    const float* __restrict__ A, unsigned* __restrict__ P, int id)
{
    int w      = id & 1023;
    int chunk  = id >> 10;
    int kchunk = chunk & 63;
    int mtile  = chunk >> 6;
    int lane = w & 31, rf = (w >> 5) & 7, kk = w >> 8;
    int row = mtile * 128 + rf * 16 + (lane >> 2);
    int col = kchunk * 32 + kk * 8 + (lane & 3);
    const float* a0 = A + (size_t)row * HID_ + col;
    ((uint4*)P)[id] = make_uint4(
        f2tf(a0[0]), f2tf(a0[8 * HID_]), f2tf(a0[4]), f2tf(a0[8 * HID_ + 4]));
}

__device__ __forceinline__ void pack_b_one(
    const float* __restrict__ W, unsigned* __restrict__ P, int N, int id)
{
    int w      = id & 2047;
    int chunk  = id >> 11;
    int kchunk = chunk & 63;
    int ntile  = chunk >> 6;
    int lane = w & 31, nb = (w >> 5) & 15, kk = w >> 9;
    int n = ntile * 128 + nb * 8 + (lane >> 2);
    int c = kchunk * 32 + kk * 8 + (lane & 3);
    ((uint2*)P)[id] = make_uint2(
        f2tf(W[(size_t)c * N + n]), f2tf(W[(size_t)(c + 4) * N + n]));
}

__global__ void pack_all(const float* __restrict__ X,
                         const float* __restrict__ Wq, const float* __restrict__ Wk,
                         const float* __restrict__ Wv, const float* __restrict__ Wo)
{
    const int NA = (BSR_ * HID_) / 4;
    const int NQ = (2048 * HID_) / 2;
    const int NK = (1024 * HID_) / 2;
    int id = blockIdx.x * blockDim.x + threadIdx.x;
    if (id < NA) { pack_a_one(X, g_Xp, id); return; }
    id -= NA;
    if (id < NQ)              { pack_b_one(Wq, g_Wqp, 2048, id); return; }
    if (id < NQ + NK)         { pack_b_one(Wk, g_Wkp, 1024, id - NQ); return; }
    if (id < NQ + 2 * NK)     { pack_b_one(Wv, g_Wvp, 1024, id - NQ - NK); return; }
    if (id < NQ + 2 * NK + NQ)  pack_b_one(Wo, g_Wop, 2048, id - NQ - 2 * NK);
}

// ============================================================
// RoPE tables
// ============================================================
__global__ void rope_table_kernel()
{
    int idx = blockIdx.x * blockDim.x + threadIdx.x;
    if (idx >= S_ * 64) return;
    int s = idx >> 6, i = idx & 63;
    const double NEG_LOG_STEP = -0.2158673524681918;
    double freq = exp((double)i * NEG_LOG_STEP);
    double sd, cd;
    sincos((double)s * freq, &sd, &cd);
    g_cos[idx] = (float)cd;
    g_sin[idx] = (float)sd;
}

// ============================================================
// TF32 GEMM core (validated): 3-stage cp.async, one barrier/chunk.
// ============================================================
#define CHUNK_BYTES 16384
#define STAGE_BYTES (2 * CHUNK_BYTES)
#define GEMM_SMEM   (3 * STAGE_BYTES)          // 98304

__device__ __forceinline__ void gemm_issue_v3(
    unsigned sbase, int stage, const unsigned* __restrict__ Ac,
    const unsigned* __restrict__ Bc, int tid)
{
    unsigned st = sbase + stage * STAGE_BYTES;
#pragma unroll
    for (int p = 0; p < 4; p++) {
        int id = tid + p * 256;
        cp16(st + id * 16,               Ac + id * 4);
        cp16(st + CHUNK_BYTES + id * 16, Bc + id * 4);
    }
    cp_commit();
}

__device__ __forceinline__ void gemm_compute_v3(
    const char* st, float acc[4][4][4], int lane, int wm, int wn)
{
    const char* sA = st;
    const char* sB = st + CHUNK_BYTES;
#pragma unroll
    for (int kk = 0; kk < 4; kk++) {
        uint4 a[4]; uint2 b[4];
#pragma unroll
        for (int mf = 0; mf < 4; mf++)
            a[mf] = *(const uint4*)(sA + (((kk * 8 + wm * 4 + mf) * 32) + lane) * 16);
#pragma unroll
        for (int nf = 0; nf < 4; nf++)
            b[nf] = *(const uint2*)(sB + (((kk * 16 + wn * 4 + nf) * 32) + lane) * 8);
#pragma unroll
        for (int mf = 0; mf < 4; mf++)
#pragma unroll
            for (int nf = 0; nf < 4; nf++)
                mma_tf32(acc[mf][nf], (const unsigned*)&a[mf], (const unsigned*)&b[nf]);
    }
}

__device__ __forceinline__ void gemm_main_v4(
    const unsigned* __restrict__ Ab, const unsigned* __restrict__ Bb,
    float acc[4][4][4], char* smem)
{
    const int tid  = threadIdx.x;
    const int lane = tid & 31;
    const int wm   = (tid >> 5) >> 2;
    const int wn   = (tid >> 5) & 3;
    unsigned sbase = (unsigned)__cvta_generic_to_shared(smem);

    gemm_issue_v3(sbase, 0, Ab, Bb, tid);
    gemm_issue_v3(sbase, 1, Ab + 4096, Bb + 4096, tid);

    for (int i = 0; i < 64; i++) {
        if (i < 63) cp_wait1(); else cp_wait0();
        __syncthreads();
        if (i + 2 < 64)
            gemm_issue_v3(sbase, (i + 2) % 3,
                          Ab + (size_t)(i + 2) * 4096,
                          Bb + (size_t)(i + 2) * 4096, tid);
        gemm_compute_v3(smem + (i % 3) * STAGE_BYTES, acc, lane, wm, wn);
    }
}

// ============================================================
// Fused QKV projections; epilogues emit flash-fragment-packed
// Q (fp16 hi-only A-frag) and K/V (fp16 hi/lo paired B-frags).
// 1024 blocks: 512 Q, 256 K, 256 V.
// ============================================================
__global__ __launch_bounds__(256, 2) void gemm_qkv(
    const unsigned* __restrict__ Ap,
    const float* __restrict__ bq, const float* __restrict__ bk,
    const float* __restrict__ bv)
{
    extern __shared__ char smem[];
    float* sf = (float*)smem;
    const int id = blockIdx.x;
    const unsigned* Bp; const float* bias;
    int bx, by, mode;
    if (id < 512)      { Bp = g_Wqp; bias = bq; bx = id & 15; by = id >> 4; mode = 0; }
    else if (id < 768) { int t = id - 512; Bp = g_Wkp; bias = bk; bx = t & 7; by = t >> 3; mode = 1; }
    else               { int t = id - 768; Bp = g_Wvp; bias = bv; bx = t & 7; by = t >> 3; mode = 2; }

    float acc[4][4][4];
#pragma unroll
    for (int i = 0; i < 4; i++)
#pragma unroll
        for (int j = 0; j < 4; j++)
#pragma unroll
            for (int e = 0; e < 4; e++) acc[i][j][e] = 0.0f;

    gemm_main_v4(Ap + (size_t)by * 64 * 4096, Bp + (size_t)bx * 64 * 4096, acc, smem);
    __syncthreads();

    const int tid  = threadIdx.x;
    const int lane = tid & 31;
    const int warp = tid >> 5;
    const int wm = warp >> 2, wn = warp & 3;

    // ---- stage tile (Q/K row-major [r][132]; V transposed [d][132]) ----
#pragma unroll
    for (int mf = 0; mf < 4; mf++) {
        int r = wm * 64 + mf * 16 + (lane >> 2);
#pragma unroll
        for (int nf = 0; nf < 4; nf++) {
            int col = wn * 32 + nf * 8 + 2 * (lane & 3);
            float b0 = bias[bx * 128 + col], b1 = bias[bx * 128 + col + 1];
            float v00 = acc[mf][nf][0] + b0, v01 = acc[mf][nf][1] + b1;
            float v10 = acc[mf][nf][2] + b0, v11 = acc[mf][nf][3] + b1;
            if (mode != 2) {
                *(float2*)(sf + r * 132 + col)       = make_float2(v00, v01);
                *(float2*)(sf + (r + 8) * 132 + col) = make_float2(v10, v11);
            } else {
                sf[col * 132 + r]           = v00;
                sf[(col + 1) * 132 + r]     = v01;
                sf[col * 132 + r + 8]       = v10;
                sf[(col + 1) * 132 + r + 8] = v11;
            }
        }
    }
    __syncthreads();

    if (mode == 0) {
        // ---- Q: rope, fp16 hi only, A-frag packed ----
        unsigned* Qh = g_Qph + (size_t)(by * 16 + bx) * 8192;
        for (int it = tid; it < 2048; it += 256) {
            int kk = it >> 8, wr = (it >> 5) & 7, ln = it & 31;
            int r = wr * 16 + (ln >> 2);
            int c = kk * 16 + 2 * (ln & 3);
            int s  = (by * 128 + r) & (S_ - 1);
            int s8 = s + 8;
            ((uint4*)Qh)[it] = make_uint4(
                pack_h2(rope_elem(sf, r, s, c),          rope_elem(sf, r, s, c + 1)),
                pack_h2(rope_elem(sf, r + 8, s8, c),     rope_elem(sf, r + 8, s8, c + 1)),
                pack_h2(rope_elem(sf, r, s, c + 8),      rope_elem(sf, r, s, c + 9)),
                pack_h2(rope_elem(sf, r + 8, s8, c + 8), rope_elem(sf, r + 8, s8, c + 9)));
        }
    } else if (mode == 1) {
        // ---- K: rope + fp16 split, paired B-frags [kt][kk8][np4][ln32] uint4 ----
        const int bb  = (by * 128) >> 11;
        const int kt0 = ((by * 128) & (S_ - 1)) >> 6;
        size_t kbase4 = ((size_t)((bb * NKV_ + bx) * 32 + kt0)) * 1024;
        for (int it = tid; it < 2048; it += 256) {
            int kt = it >> 10, w = it & 1023;
            int kk = w >> 7, np = (w >> 5) & 3, ln = w & 31;
            int c = kk * 16 + 2 * (ln & 3);
            unsigned hv[4], lv[4];
#pragma unroll
            for (int p = 0; p < 2; p++) {
                int n = (2 * np + p) * 8 + (ln >> 2);
                int r = kt * 64 + n;
                int s = (by * 128 + r) & (S_ - 1);
                float e0 = rope_elem(sf, r, s, c);
                float e1 = rope_elem(sf, r, s, c + 1);
                float e2 = rope_elem(sf, r, s, c + 8);
                float e3 = rope_elem(sf, r, s, c + 9);
                split2h(e0, e1, hv[2*p],   lv[2*p]);
                split2h(e2, e3, hv[2*p+1], lv[2*p+1]);
            }
            ((uint4*)g_Kph)[kbase4 + kt * 1024 + w] = make_uint4(hv[0], hv[1], hv[2], hv[3]);
            ((uint4*)g_Kpl)[kbase4 + kt * 1024 + w] = make_uint4(lv[0], lv[1], lv[2], lv[3]);
        }
    } else {
        // ---- V: fp16 split, paired transposed B-frags [kt][kk2 4][np8][ln32] uint4 ----
        const int bb  = (by * 128) >> 11;
        const int kt0 = ((by * 128) & (S_ - 1)) >> 6;
        size_t vbase4 = ((size_t)((bb * NKV_ + bx) * 32 + kt0)) * 1024;
        for (int it = tid; it < 2048; it += 256) {
            int kt = it >> 10, w = it & 1023;
            int kk2 = w >> 8, np = (w >> 5) & 7, ln = w & 31;
            int cl = kk2 * 16 + 2 * (ln & 3);
            int r  = kt * 64 + cl;
            unsigned hv[4], lv[4];
#pragma unroll
            for (int p = 0; p < 2; p++) {
                int n = (2 * np + p) * 8 + (ln >> 2);
                float e0 = sf[n * 132 + r],     e1 = sf[n * 132 + r + 1];
                float e2 = sf[n * 132 + r + 8], e3 = sf[n * 132 + r + 9];
                split2h(e0, e1, hv[2*p],   lv[2*p]);
                split2h(e2, e3, hv[2*p+1], lv[2*p+1]);
            }
            ((uint4*)g_Vph)[vbase4 + kt * 1024 + w] = make_uint4(hv[0], hv[1], hv[2], hv[3]);
            ((uint4*)g_Vpl)[vbase4 + kt * 1024 + w] = make_uint4(lv[0], lv[1], lv[2], lv[3]);
        }
    }
}

// ============================================================
// O projection GEMM (unchanged)
// ============================================================
__global__ __launch_bounds__(256, 2) void gemm_v3(
    const unsigned* __restrict__ Ap, const unsigned* __restrict__ Bp,
    float* __restrict__ C, int N)
{
    extern __shared__ char smem[];
    float acc[4][4][4];
#pragma unroll
    for (int i = 0; i < 4; i++)
#pragma unroll
        for (int j = 0; j < 4; j++)
#pragma unroll
            for (int e = 0; e < 4; e++) acc[i][j][e] = 0.0f;

    gemm_main_v4(Ap + (size_t)blockIdx.y * 64 * 4096,
                 Bp + (size_t)blockIdx.x * 64 * 4096, acc, smem);

    const int lane = threadIdx.x & 31;
    const int warp = threadIdx.x >> 5;
    const int wm = warp >> 2, wn = warp & 3;
#pragma unroll
    for (int mf = 0; mf < 4; mf++) {
        int row = blockIdx.y * 128 + wm * 64 + mf * 16 + (lane >> 2);
#pragma unroll
        for (int nf = 0; nf < 4; nf++) {
            int col = blockIdx.x * 128 + wn * 32 + nf * 8 + 2 * (lane & 3);
            *(float2*)&C[(size_t)row * N + col] =
                make_float2(acc[mf][nf][0], acc[mf][nf][1]);
            *(float2*)&C[(size_t)(row + 8) * N + col] =
                make_float2(acc[mf][nf][2], acc[mf][nf][3]);
        }
    }
}

// ============================================================
// Flash attention: fp16 2-split (Q hi · K hi/lo; P hi · V hi/lo),
// paired-fragment LDS.128, register softmax, ctx A-pack epilogue.
// smem: QH 32K | 2 stages x (Kh16K Kl16K Vh16K Vl16K)
// ============================================================
#define BQ 128
#define QH_OFF 0
#define ST0_OFF 32768
#define FSTAGE 65536
#define FLASH_SMEM (ST0_OFF + 2 * FSTAGE)     // 163840

__device__ __forceinline__ void flash_issue(
    unsigned sbase, int stage, size_t base_u, int tid)
{
    unsigned st = sbase + ST0_OFF + stage * FSTAGE;
#pragma unroll
    for (int p = 0; p < 4; p++) {
        int id = tid + p * 256;                 // 0..1023
        cp16(st + id * 16,         g_Kph + base_u + id * 4);
        cp16(st + 16384 + id * 16, g_Kpl + base_u + id * 4);
        cp16(st + 32768 + id * 16, g_Vph + base_u + id * 4);
        cp16(st + 49152 + id * 16, g_Vpl + base_u + id * 4);
    }
    cp_commit();
}

__global__ __launch_bounds__(256, 1) void flash_f16()
{
    extern __shared__ char sm[];
    const int tid  = threadIdx.x;
    const int lane = tid & 31;
    const int warp = tid >> 5;
    const int qtile = (gridDim.x - 1) - blockIdx.x;
    const int h    = blockIdx.y;
    const int b    = blockIdx.z;
    const int kvh  = h / G_;
    const int qbase = qtile * BQ;
    const float scale = 0.08838834764831845f;
    const int g = lane >> 2;
    const int t = lane & 3;
    const int m0 = warp * 16;
    unsigned sbase = (unsigned)__cvta_generic_to_shared(sm);

    const size_t kvstep = 4096;                       // unsigned per 64-key tile
    const size_t kvb0 = ((size_t)(b * NKV_ + kvh) * 32) * kvstep;

    flash_issue(sbase, 0, kvb0, tid);

    // Q tile: linear copy of packed hi fragments
    {
        const int mq = (b * S_ + qbase) >> 7;
        const uint4* qh = (const uint4*)g_Qph + (size_t)(mq * 16 + h) * 2048;
        for (int it = tid; it < 2048; it += 256)
            *(uint4*)(sm + QH_OFF + it * 16) = qh[it];
    }

    float ctx[16][4];
#pragma unroll
    for (int i = 0; i < 16; i++)
#pragma unroll
        for (int e = 0; e < 4; e++) ctx[i][e] = 0.0f;
    float mr0 = -INFINITY, mr1 = -INFINITY, lr0 = 0.0f, lr1 = 0.0f;

    const int row0 = qbase + m0 + g;
    const int row1 = row0 + 8;
    const int ntile = 2 * qtile + 2;

    for (int j = 0; j < ntile; j++) {
        const int kb = j * 64;
        if (j + 1 < ntile) {
            flash_issue(sbase, (j + 1) & 1, kvb0 + (size_t)(j + 1) * kvstep, tid);
            cp_wait1();
        } else {
            cp_wait0();
        }
        __syncthreads();

        const char* stg  = sm + ST0_OFF + (j & 1) * FSTAGE;
        const char* stK  = stg;
        const char* stKL = stg + 16384;
        const char* stV  = stg + 32768;
        const char* stVL = stg + 49152;

        float acc[8][4];
#pragma unroll
        for (int nf = 0; nf < 8; nf++)
#pragma unroll
            for (int e = 0; e < 4; e++) acc[nf][e] = 0.0f;

        // ---- QK: qH · (kH + kL) ----
#pragma unroll
        for (int kk = 0; kk < 8; kk++) {
            uint4 aH = *(const uint4*)(sm + QH_OFF + (kk * 256 + warp * 32 + lane) * 16);
#pragma unroll
            for (int np = 0; np < 4; np++) {
                uint4 bH2 = *(const uint4*)(stK  + (kk * 128 + np * 32 + lane) * 16);
                uint4 bL2 = *(const uint4*)(stKL + (kk * 128 + np * 32 + lane) * 16);
                const unsigned* bh = (const unsigned*)&bH2;
                const unsigned* bl = (const unsigned*)&bL2;
                mma_f16(acc[2*np],     (const unsigned*)&aH, bh);
                mma_f16(acc[2*np],     (const unsigned*)&aH, bl);
                mma_f16(acc[2*np + 1], (const unsigned*)&aH, bh + 2);
                mma_f16(acc[2*np + 1], (const unsigned*)&aH, bl + 2);
            }
        }

#pragma unroll
        for (int nf = 0; nf < 8; nf++)
#pragma unroll
            for (int e = 0; e < 4; e++) acc[nf][e] *= scale;

        if (kb + 63 > qbase + m0) {
#pragma unroll
            for (int nf = 0; nf < 8; nf++) {
                int k0 = kb + nf * 8 + 2 * t;
                if (k0     > row0) acc[nf][0] = -INFINITY;
                if (k0 + 1 > row0) acc[nf][1] = -INFINITY;
                if (k0     > row1) acc[nf][2] = -INFINITY;
                if (k0 + 1 > row1) acc[nf][3] = -INFINITY;
            }
        }

        float mx0 = -INFINITY, mx1 = -INFINITY;
#pragma unroll
        for (int nf = 0; nf < 8; nf++) {
            mx0 = fmaxf(mx0, fmaxf(acc[nf][0], acc[nf][1]));
            mx1 = fmaxf(mx1, fmaxf(acc[nf][2], acc[nf][3]));
        }
        mx0 = fmaxf(mx0, __shfl_xor_sync(0xffffffffu, mx0, 1));
        mx0 = fmaxf(mx0, __shfl_xor_sync(0xffffffffu, mx0, 2));
        mx1 = fmaxf(mx1, __shfl_xor_sync(0xffffffffu, mx1, 1));
        mx1 = fmaxf(mx1, __shfl_xor_sync(0xffffffffu, mx1, 2));

        float mn0 = fmaxf(mr0, mx0);
        float mn1 = fmaxf(mr1, mx1);
        float al0 = __expf(mr0 - mn0);
        float al1 = __expf(mr1 - mn1);
        mr0 = mn0; mr1 = mn1;

        unsigned pH[4][4];
        float s0 = 0.0f, s1 = 0.0f;
#pragma unroll
        for (int nf = 0; nf < 8; nf++) {
            float p00 = __expf(acc[nf][0] - mn0);
            float p01 = __expf(acc[nf][1] - mn0);
            float p10 = __expf(acc[nf][2] - mn1);
            float p11 = __expf(acc[nf][3] - mn1);
            s0 += p00 + p01;
            s1 += p10 + p11;
            int kk2 = nf >> 1;
            int sl  = (nf & 1) << 1;
            pH[kk2][sl]     = pack_h2(p00, p01);
            pH[kk2][sl + 1] = pack_h2(p10, p11);
        }
        s0 += __shfl_xor_sync(0xffffffffu, s0, 1);
        s0 += __shfl_xor_sync(0xffffffffu, s0, 2);
        s1 += __shfl_xor_sync(0xffffffffu, s1, 1);
        s1 += __shfl_xor_sync(0xffffffffu, s1, 2);
        lr0 = lr0 * al0 + s0;
        lr1 = lr1 * al1 + s1;

#pragma unroll
        for (int nf = 0; nf < 16; nf++) {
            ctx[nf][0] *= al0; ctx[nf][1] *= al0;
            ctx[nf][2] *= al1; ctx[nf][3] *= al1;
        }
        // ---- PV: pH · (vH + vL) ----
#pragma unroll
        for (int kk2 = 0; kk2 < 4; kk2++) {
#pragma unroll
            for (int np = 0; np < 8; np++) {
                uint4 vH2 = *(const uint4*)(stV  + (kk2 * 256 + np * 32 + lane) * 16);
                uint4 vL2 = *(const uint4*)(stVL + (kk2 * 256 + np * 32 + lane) * 16);
                const unsigned* vh = (const unsigned*)&vH2;
                const unsigned* vl = (const unsigned*)&vL2;
                mma_f16(ctx[2*np],     pH[kk2], vh);
                mma_f16(ctx[2*np],     pH[kk2], vl);
                mma_f16(ctx[2*np + 1], pH[kk2], vh + 2);
                mma_f16(ctx[2*np + 1], pH[kk2], vl + 2);
            }
        }
        __syncthreads();
    }

    // ---- fused epilogue: stage ctx f32, emit A-packed tf32 g_Ctp ----
    float* cs = (float*)(sm + ST0_OFF);        // 128x132 f32
    {
        float il0 = 1.0f / lr0;
        float il1 = 1.0f / lr1;
        int rl0 = m0 + g;
#pragma unroll
        for (int nf = 0; nf < 16; nf++) {
            int d = nf * 8 + 2 * t;
            *(float2*)(cs + rl0 * 132 + d) =
                make_float2(ctx[nf][0] * il0, ctx[nf][1] * il0);
            *(float2*)(cs + (rl0 + 8) * 132 + d) =
                make_float2(ctx[nf][2] * il1, ctx[nf][3] * il1);
        }
    }
    __syncthreads();

    {
        const int mtile = (b * S_ + qbase) >> 7;
        for (int it = tid; it < 4096; it += 256) {
            int ln = it & 31, rf = (it >> 5) & 7, kk = (it >> 8) & 3, kc = it >> 10;
            int rl = rf * 16 + (ln >> 2);
            int cl = kc * 32 + kk * 8 + (ln & 3);
            uint4 o = make_uint4(
                f2tf(cs[rl * 132 + cl]),       f2tf(cs[(rl + 8) * 132 + cl]),
                f2tf(cs[rl * 132 + cl + 4]),   f2tf(cs[(rl + 8) * 132 + cl + 4]));
            size_t idx = ((size_t)(mtile * 64 + h * 4 + kc) << 10) +
                         (kk << 8) + (rf << 5) + ln;
            ((uint4*)g_Ctp)[idx] = o;
        }
    }
}

// ============================================================
// launch
// ============================================================
extern "C" void kernel_launch(void* const* d_in, const int* in_sizes, int n_in,
                              void* d_out, int out_size)
{
    (void)in_sizes; (void)n_in; (void)out_size;
    const float* hidden = (const float*)d_in[0];
    const float* Wq = (const float*)d_in[1];
    const float* bq = (const float*)d_in[2];
    const float* Wk = (const float*)d_in[3];
    const float* bk = (const float*)d_in[4];
    const float* Wv = (const float*)d_in[5];
    const float* bv = (const float*)d_in[6];
    const float* Wo = (const float*)d_in[7];
    float* out = (float*)d_out;

    unsigned *xp, *ctp, *wop;
    cudaGetSymbolAddress((void**)&xp,  g_Xp);
    cudaGetSymbolAddress((void**)&ctp, g_Ctp);
    cudaGetSymbolAddress((void**)&wop, g_Wop);

    cudaFuncSetAttribute(gemm_qkv,
        cudaFuncAttributeMaxDynamicSharedMemorySize, GEMM_SMEM);
    cudaFuncSetAttribute(gemm_v3,
        cudaFuncAttributeMaxDynamicSharedMemorySize, GEMM_SMEM);
    cudaFuncSetAttribute(flash_f16,
        cudaFuncAttributeMaxDynamicSharedMemorySize, FLASH_SMEM);

    const int NPACK = BSR_ * HID_ / 4 + (2048 + 1024 + 1024 + 2048) * HID_ / 2;

    // 1: pack GEMM operands
    pack_all<<<(NPACK + 255) / 256, 256>>>(hidden, Wq, Wk, Wv, Wo);
    // 2: RoPE tables
    rope_table_kernel<<<(S_ * 64 + 255) / 256, 256>>>();
    // 3: fused QKV projections + fp16 fragment epilogues
    gemm_qkv<<<1024, 256, GEMM_SMEM>>>(xp, bq, bk, bv);
    // 4: flash attention (fp16 2-split)  ← profiled launch
    flash_f16<<<dim3(S_ / BQ, NH_, B_), 256, FLASH_SMEM>>>();
    // 5: O projection → final output
    gemm_v3<<<dim3(16, 32), 256, GEMM_SMEM>>>(ctp, wop, out, HID_);
}

// round 14
// speedup vs baseline: 1.5806x; 1.4415x over previous
#include <cuda_runtime.h>
#include <cuda_bf16.h>
#include <cuda_fp16.h>
#include <math.h>

#define B_    2
#define S_    2048
#define HID_  2048
#define NH_   16
#define NKV_  8
#define D_    128
#define G_    (NH_/NKV_)
#define BSR_  (B_*S_)          // 4096

// -------- scratch (__device__ globals; no allocations) --------
// flash operands, mma-fragment-packed fp16 (validated R13)
__device__ unsigned g_Qph[BSR_ * NH_ * D_ / 2];     // [rowblk32*NH_][kk8][wr8][ln32] uint4
__device__ unsigned g_Kph[BSR_ * NKV_ * D_ / 2];    // [b2][kvh8][kt32][kk8][np4][ln32] uint4
__device__ unsigned g_Kpl[BSR_ * NKV_ * D_ / 2];
__device__ unsigned g_Vph[BSR_ * NKV_ * D_ / 2];    // [b2][kvh8][kt32][kk2 4][np8][ln32] uint4
__device__ unsigned g_Vpl[BSR_ * NKV_ * D_ / 2];
// GEMM operands, fragment-packed FP16 (half the tf32 footprint)
__device__ unsigned g_Xp [BSR_ * HID_ / 2];         // A-pack: [mtile][kc32][kk4][rf8][ln32] uint4
__device__ unsigned g_Ctp[BSR_ * NH_ * D_ / 2];
__device__ unsigned g_Wqp[HID_ * NH_ * D_ / 2];     // B-pack: [ntile][kc32][kk4][nb16][ln32] uint2
__device__ unsigned g_Wkp[HID_ * NKV_ * D_ / 2];
__device__ unsigned g_Wvp[HID_ * NKV_ * D_ / 2];
__device__ unsigned g_Wop[NH_ * D_ * HID_ / 2];
__device__ float g_cos[S_ * 64];
__device__ float g_sin[S_ * 64];

// ---------------- helpers ----------------
__device__ __forceinline__ void cp16(unsigned dst, const void* src) {
    asm volatile("cp.async.cg.shared.global [%0], [%1], 16;" :: "r"(dst), "l"(src));
}
__device__ __forceinline__ void cp_commit() { asm volatile("cp.async.commit_group;"); }
__device__ __forceinline__ void cp_wait1()  { asm volatile("cp.async.wait_group 1;"); }
__device__ __forceinline__ void cp_wait0()  { asm volatile("cp.async.wait_group 0;"); }

__device__ __forceinline__ unsigned pack_h2(float x, float y) {
    __half2 h;
    h.x = __float2half_rn(x);
    h.y = __float2half_rn(y);
    return *(unsigned*)&h;
}
__device__ __forceinline__ void split2h(float x, float y, unsigned& hi, unsigned& lo) {
    __half hx = __float2half_rn(x);
    __half hy = __float2half_rn(y);
    float rx = x - __half2float(hx);
    float ry = y - __half2float(hy);
    __half2 h; h.x = hx; h.y = hy;
    __half2 l; l.x = __float2half_rn(rx); l.y = __float2half_rn(ry);
    hi = *(unsigned*)&h;
    lo = *(unsigned*)&l;
}

__device__ __forceinline__ void mma_f16(float* d, const unsigned* a, const unsigned* b) {
    asm volatile(
        "mma.sync.aligned.m16n8k16.row.col.f32.f16.f16.f32 "
        "{%0,%1,%2,%3}, {%4,%5,%6,%7}, {%8,%9}, {%0,%1,%2,%3};\n"
        : "+f"(d[0]), "+f"(d[1]), "+f"(d[2]), "+f"(d[3])
        : "r"(a[0]), "r"(a[1]), "r"(a[2]), "r"(a[3]), "r"(b[0]), "r"(b[1]));
}

__device__ __forceinline__ float rope_elem(const float* sf, int r, int s, int c) {
    if (c < 64)
        return sf[r * 132 + c] * g_cos[s * 64 + c] - sf[r * 132 + c + 64] * g_sin[s * 64 + c];
    int i = c - 64;
    return sf[r * 132 + c] * g_cos[s * 64 + i] + sf[r * 132 + c - 64] * g_sin[s * 64 + i];
}

// ============================================================
// FP16 fragment packing of GEMM operands.
// A-pack: uint4 = {h2(A[r][c],A[r][c+1]), h2(A[r+8][c],..), h2(A[r][c+8],..), h2(A[r+8][c+8],..)}
//   r = mtile*128 + rf*16 + (ln>>2), c = kchunk*64 + kk*16 + 2(ln&3)
// B-pack: uint2 = {h2(W[c][n],W[c+1][n]), h2(W[c+8][n],W[c+9][n])}
//   n = ntile*128 + nb*8 + (ln>>2)
// Chunk (K=64): A 1024 uint4 = 16KB, B 2048 uint2 = 16KB.
// ============================================================
__device__ __forceinline__ void pack_a_one(
    const float* __restrict__ A, unsigned* __restrict__ P, int id)
{
    int w      = id & 1023;
    int chunk  = id >> 10;
    int kchunk = chunk & 31;
    int mtile  = chunk >> 5;
    int lane = w & 31, rf = (w >> 5) & 7, kk = w >> 8;
    int row = mtile * 128 + rf * 16 + (lane >> 2);
    int col = kchunk * 64 + kk * 16 + 2 * (lane & 3);
    const float* a0 = A + (size_t)row * HID_ + col;
    ((uint4*)P)[id] = make_uint4(
        pack_h2(a0[0], a0[1]),
        pack_h2(a0[8 * HID_], a0[8 * HID_ + 1]),
        pack_h2(a0[8], a0[9]),
        pack_h2(a0[8 * HID_ + 8], a0[8 * HID_ + 9]));
}

__device__ __forceinline__ void pack_b_one(
    const float* __restrict__ W, unsigned* __restrict__ P, int N, int id)
{
    int w      = id & 2047;
    int chunk  = id >> 11;
    int kchunk = chunk & 31;
    int ntile  = chunk >> 5;
    int lane = w & 31, nb = (w >> 5) & 15, kk = w >> 9;
    int n = ntile * 128 + nb * 8 + (lane >> 2);
    int c = kchunk * 64 + kk * 16 + 2 * (lane & 3);
    ((uint2*)P)[id] = make_uint2(
        pack_h2(W[(size_t)c * N + n],       W[(size_t)(c + 1) * N + n]),
        pack_h2(W[(size_t)(c + 8) * N + n], W[(size_t)(c + 9) * N + n]));
}

__global__ void pack_all(const float* __restrict__ X,
                         const float* __restrict__ Wq, const float* __restrict__ Wk,
                         const float* __restrict__ Wv, const float* __restrict__ Wo)
{
    const int NA = (BSR_ * HID_) / 8;       // uint4 jobs
    const int NQ = (2048 * HID_) / 4;       // uint2 jobs
    const int NK = (1024 * HID_) / 4;
    int id = blockIdx.x * blockDim.x + threadIdx.x;
    if (id < NA) { pack_a_one(X, g_Xp, id); return; }
    id -= NA;
    if (id < NQ)              { pack_b_one(Wq, g_Wqp, 2048, id); return; }
    if (id < NQ + NK)         { pack_b_one(Wk, g_Wkp, 1024, id - NQ); return; }
    if (id < NQ + 2 * NK)     { pack_b_one(Wv, g_Wvp, 1024, id - NQ - NK); return; }
    if (id < NQ + 2 * NK + NQ)  pack_b_one(Wo, g_Wop, 2048, id - NQ - 2 * NK);
}

// ============================================================
// RoPE tables
// ============================================================
__global__ void rope_table_kernel()
{
    int idx = blockIdx.x * blockDim.x + threadIdx.x;
    if (idx >= S_ * 64) return;
    int s = idx >> 6, i = idx & 63;
    const double NEG_LOG_STEP = -0.2158673524681918;
    double freq = exp((double)i * NEG_LOG_STEP);
    double sd, cd;
    sincos((double)s * freq, &sd, &cd);
    g_cos[idx] = (float)cd;
    g_sin[idx] = (float)sd;
}

// ============================================================
// FP16 GEMM core: K-chunk 64, 3-stage cp.async, one barrier/chunk.
// ============================================================
#define CHUNK_BYTES 16384                       // per operand per chunk
#define STAGE_BYTES (2 * CHUNK_BYTES)
#define GEMM_SMEM   (3 * STAGE_BYTES)           // 98304

__device__ __forceinline__ void gemm_issue_h(
    unsigned sbase, int stage, const unsigned* __restrict__ Ac,
    const unsigned* __restrict__ Bc, int tid)
{
    unsigned st = sbase + stage * STAGE_BYTES;
#pragma unroll
    for (int p = 0; p < 4; p++) {
        int id = tid + p * 256;
        cp16(st + id * 16,               Ac + id * 4);
        cp16(st + CHUNK_BYTES + id * 16, Bc + id * 4);
    }
    cp_commit();
}

__device__ __forceinline__ void gemm_compute_h(
    const char* st, float acc[4][4][4], int lane, int wm, int wn)
{
    const char* sA = st;
    const char* sB = st + CHUNK_BYTES;
#pragma unroll
    for (int kk = 0; kk < 4; kk++) {
        uint4 a[4]; uint2 b[4];
#pragma unroll
        for (int mf = 0; mf < 4; mf++)
            a[mf] = *(const uint4*)(sA + (((kk * 8 + wm * 4 + mf) * 32) + lane) * 16);
#pragma unroll
        for (int nf = 0; nf < 4; nf++)
            b[nf] = *(const uint2*)(sB + (((kk * 16 + wn * 4 + nf) * 32) + lane) * 8);
#pragma unroll
        for (int mf = 0; mf < 4; mf++)
#pragma unroll
            for (int nf = 0; nf < 4; nf++)
                mma_f16(acc[mf][nf], (const unsigned*)&a[mf], (const unsigned*)&b[nf]);
    }
}

// 32 chunks of K=64 (K=2048 total)
__device__ __forceinline__ void gemm_main_h(
    const unsigned* __restrict__ Ab, const unsigned* __restrict__ Bb,
    float acc[4][4][4], char* smem)
{
    const int tid  = threadIdx.x;
    const int lane = tid & 31;
    const int wm   = (tid >> 5) >> 2;
    const int wn   = (tid >> 5) & 3;
    unsigned sbase = (unsigned)__cvta_generic_to_shared(smem);

    gemm_issue_h(sbase, 0, Ab, Bb, tid);
    gemm_issue_h(sbase, 1, Ab + 4096, Bb + 4096, tid);

    for (int i = 0; i < 32; i++) {
        if (i < 31) cp_wait1(); else cp_wait0();
        __syncthreads();
        if (i + 2 < 32)
            gemm_issue_h(sbase, (i + 2) % 3,
                         Ab + (size_t)(i + 2) * 4096,
                         Bb + (size_t)(i + 2) * 4096, tid);
        gemm_compute_h(smem + (i % 3) * STAGE_BYTES, acc, lane, wm, wn);
    }
}

// ============================================================
// Fused QKV projections; epilogues emit flash-fragment-packed
// Q (fp16 A-frag) and K/V (fp16 hi/lo paired B-frags). (R13 epilogues)
// ============================================================
__global__ __launch_bounds__(256, 2) void gemm_qkv(
    const unsigned* __restrict__ Ap,
    const float* __restrict__ bq, const float* __restrict__ bk,
    const float* __restrict__ bv)
{
    extern __shared__ char smem[];
    float* sf = (float*)smem;
    const int id = blockIdx.x;
    const unsigned* Bp; const float* bias;
    int bx, by, mode;
    if (id < 512)      { Bp = g_Wqp; bias = bq; bx = id & 15; by = id >> 4; mode = 0; }
    else if (id < 768) { int t = id - 512; Bp = g_Wkp; bias = bk; bx = t & 7; by = t >> 3; mode = 1; }
    else               { int t = id - 768; Bp = g_Wvp; bias = bv; bx = t & 7; by = t >> 3; mode = 2; }

    float acc[4][4][4];
#pragma unroll
    for (int i = 0; i < 4; i++)
#pragma unroll
        for (int j = 0; j < 4; j++)
#pragma unroll
            for (int e = 0; e < 4; e++) acc[i][j][e] = 0.0f;

    gemm_main_h(Ap + (size_t)by * 32 * 4096, Bp + (size_t)bx * 32 * 4096, acc, smem);
    __syncthreads();

    const int tid  = threadIdx.x;
    const int lane = tid & 31;
    const int warp = tid >> 5;
    const int wm = warp >> 2, wn = warp & 3;

    // ---- stage tile (Q/K row-major [r][132]; V transposed [d][132]) ----
#pragma unroll
    for (int mf = 0; mf < 4; mf++) {
        int r = wm * 64 + mf * 16 + (lane >> 2);
#pragma unroll
        for (int nf = 0; nf < 4; nf++) {
            int col = wn * 32 + nf * 8 + 2 * (lane & 3);
            float b0 = bias[bx * 128 + col], b1 = bias[bx * 128 + col + 1];
            float v00 = acc[mf][nf][0] + b0, v01 = acc[mf][nf][1] + b1;
            float v10 = acc[mf][nf][2] + b0, v11 = acc[mf][nf][3] + b1;
            if (mode != 2) {
                *(float2*)(sf + r * 132 + col)       = make_float2(v00, v01);
                *(float2*)(sf + (r + 8) * 132 + col) = make_float2(v10, v11);
            } else {
                sf[col * 132 + r]           = v00;
                sf[(col + 1) * 132 + r]     = v01;
                sf[col * 132 + r + 8]       = v10;
                sf[(col + 1) * 132 + r + 8] = v11;
            }
        }
    }
    __syncthreads();

    if (mode == 0) {
        unsigned* Qh = g_Qph + (size_t)(by * 16 + bx) * 8192;
        for (int it = tid; it < 2048; it += 256) {
            int kk = it >> 8, wr = (it >> 5) & 7, ln = it & 31;
            int r = wr * 16 + (ln >> 2);
            int c = kk * 16 + 2 * (ln & 3);
            int s  = (by * 128 + r) & (S_ - 1);
            int s8 = s + 8;
            ((uint4*)Qh)[it] = make_uint4(
                pack_h2(rope_elem(sf, r, s, c),          rope_elem(sf, r, s, c + 1)),
                pack_h2(rope_elem(sf, r + 8, s8, c),     rope_elem(sf, r + 8, s8, c + 1)),
                pack_h2(rope_elem(sf, r, s, c + 8),      rope_elem(sf, r, s, c + 9)),
                pack_h2(rope_elem(sf, r + 8, s8, c + 8), rope_elem(sf, r + 8, s8, c + 9)));
        }
    } else if (mode == 1) {
        const int bb  = (by * 128) >> 11;
        const int kt0 = ((by * 128) & (S_ - 1)) >> 6;
        size_t kbase4 = ((size_t)((bb * NKV_ + bx) * 32 + kt0)) * 1024;
        for (int it = tid; it < 2048; it += 256) {
            int kt = it >> 10, w = it & 1023;
            int kk = w >> 7, np = (w >> 5) & 3, ln = w & 31;
            int c = kk * 16 + 2 * (ln & 3);
            unsigned hv[4], lv[4];
#pragma unroll
            for (int p = 0; p < 2; p++) {
                int n = (2 * np + p) * 8 + (ln >> 2);
                int r = kt * 64 + n;
                int s = (by * 128 + r) & (S_ - 1);
                float e0 = rope_elem(sf, r, s, c);
                float e1 = rope_elem(sf, r, s, c + 1);
                float e2 = rope_elem(sf, r, s, c + 8);
                float e3 = rope_elem(sf, r, s, c + 9);
                split2h(e0, e1, hv[2*p],   lv[2*p]);
                split2h(e2, e3, hv[2*p+1], lv[2*p+1]);
            }
            ((uint4*)g_Kph)[kbase4 + kt * 1024 + w] = make_uint4(hv[0], hv[1], hv[2], hv[3]);
            ((uint4*)g_Kpl)[kbase4 + kt * 1024 + w] = make_uint4(lv[0], lv[1], lv[2], lv[3]);
        }
    } else {
        const int bb  = (by * 128) >> 11;
        const int kt0 = ((by * 128) & (S_ - 1)) >> 6;
        size_t vbase4 = ((size_t)((bb * NKV_ + bx) * 32 + kt0)) * 1024;
        for (int it = tid; it < 2048; it += 256) {
            int kt = it >> 10, w = it & 1023;
            int kk2 = w >> 8, np = (w >> 5) & 7, ln = w & 31;
            int cl = kk2 * 16 + 2 * (ln & 3);
            int r  = kt * 64 + cl;
            unsigned hv[4], lv[4];
#pragma unroll
            for (int p = 0; p < 2; p++) {
                int n = (2 * np + p) * 8 + (ln >> 2);
                float e0 = sf[n * 132 + r],     e1 = sf[n * 132 + r + 1];
                float e2 = sf[n * 132 + r + 8], e3 = sf[n * 132 + r + 9];
                split2h(e0, e1, hv[2*p],   lv[2*p]);
                split2h(e2, e3, hv[2*p+1], lv[2*p+1]);
            }
            ((uint4*)g_Vph)[vbase4 + kt * 1024 + w] = make_uint4(hv[0], hv[1], hv[2], hv[3]);
            ((uint4*)g_Vpl)[vbase4 + kt * 1024 + w] = make_uint4(lv[0], lv[1], lv[2], lv[3]);
        }
    }
}

// ============================================================
// O projection GEMM (fp16 core, writes final out)
// ============================================================
__global__ __launch_bounds__(256, 2) void gemm_v3(
    const unsigned* __restrict__ Ap, const unsigned* __restrict__ Bp,
    float* __restrict__ C, int N)
{
    extern __shared__ char smem[];
    float acc[4][4][4];
#pragma unroll
    for (int i = 0; i < 4; i++)
#pragma unroll
        for (int j = 0; j < 4; j++)
#pragma unroll
            for (int e = 0; e < 4; e++) acc[i][j][e] = 0.0f;

    gemm_main_h(Ap + (size_t)blockIdx.y * 32 * 4096,
                Bp + (size_t)blockIdx.x * 32 * 4096, acc, smem);

    const int lane = threadIdx.x & 31;
    const int warp = threadIdx.x >> 5;
    const int wm = warp >> 2, wn = warp & 3;
#pragma unroll
    for (int mf = 0; mf < 4; mf++) {
        int row = blockIdx.y * 128 + wm * 64 + mf * 16 + (lane >> 2);
#pragma unroll
        for (int nf = 0; nf < 4; nf++) {
            int col = blockIdx.x * 128 + wn * 32 + nf * 8 + 2 * (lane & 3);
            *(float2*)&C[(size_t)row * N + col] =
                make_float2(acc[mf][nf][0], acc[mf][nf][1]);
            *(float2*)&C[(size_t)(row + 8) * N + col] =
                make_float2(acc[mf][nf][2], acc[mf][nf][3]);
        }
    }
}

// ============================================================
// Flash attention (R13, validated): fp16 2-split, paired frags.
// Epilogue now emits fp16 A-packed ctx.
// smem: QH 32K | 2 stages x (Kh16K Kl16K Vh16K Vl16K)
// ============================================================
#define BQ 128
#define QH_OFF 0
#define ST0_OFF 32768
#define FSTAGE 65536
#define FLASH_SMEM (ST0_OFF + 2 * FSTAGE)     // 163840

__device__ __forceinline__ void flash_issue(
    unsigned sbase, int stage, size_t base_u, int tid)
{
    unsigned st = sbase + ST0_OFF + stage * FSTAGE;
#pragma unroll
    for (int p = 0; p < 4; p++) {
        int id = tid + p * 256;
        cp16(st + id * 16,         g_Kph + base_u + id * 4);
        cp16(st + 16384 + id * 16, g_Kpl + base_u + id * 4);
        cp16(st + 32768 + id * 16, g_Vph + base_u + id * 4);
        cp16(st + 49152 + id * 16, g_Vpl + base_u + id * 4);
    }
    cp_commit();
}

__global__ __launch_bounds__(256, 1) void flash_f16()
{
    extern __shared__ char sm[];
    const int tid  = threadIdx.x;
    const int lane = tid & 31;
    const int warp = tid >> 5;
    const int qtile = (gridDim.x - 1) - blockIdx.x;
    const int h    = blockIdx.y;
    const int b    = blockIdx.z;
    const int kvh  = h / G_;
    const int qbase = qtile * BQ;
    const float scale = 0.08838834764831845f;
    const int g = lane >> 2;
    const int t = lane & 3;
    const int m0 = warp * 16;
    unsigned sbase = (unsigned)__cvta_generic_to_shared(sm);

    const size_t kvstep = 4096;
    const size_t kvb0 = ((size_t)(b * NKV_ + kvh) * 32) * kvstep;

    flash_issue(sbase, 0, kvb0, tid);

    {
        const int mq = (b * S_ + qbase) >> 7;
        const uint4* qh = (const uint4*)g_Qph + (size_t)(mq * 16 + h) * 2048;
        for (int it = tid; it < 2048; it += 256)
            *(uint4*)(sm + QH_OFF + it * 16) = qh[it];
    }

    float ctx[16][4];
#pragma unroll
    for (int i = 0; i < 16; i++)
#pragma unroll
        for (int e = 0; e < 4; e++) ctx[i][e] = 0.0f;
    float mr0 = -INFINITY, mr1 = -INFINITY, lr0 = 0.0f, lr1 = 0.0f;

    const int row0 = qbase + m0 + g;
    const int row1 = row0 + 8;
    const int ntile = 2 * qtile + 2;

    for (int j = 0; j < ntile; j++) {
        const int kb = j * 64;
        if (j + 1 < ntile) {
            flash_issue(sbase, (j + 1) & 1, kvb0 + (size_t)(j + 1) * kvstep, tid);
            cp_wait1();
        } else {
            cp_wait0();
        }
        __syncthreads();

        const char* stg  = sm + ST0_OFF + (j & 1) * FSTAGE;
        const char* stK  = stg;
        const char* stKL = stg + 16384;
        const char* stV  = stg + 32768;
        const char* stVL = stg + 49152;

        float acc[8][4];
#pragma unroll
        for (int nf = 0; nf < 8; nf++)
#pragma unroll
            for (int e = 0; e < 4; e++) acc[nf][e] = 0.0f;

#pragma unroll
        for (int kk = 0; kk < 8; kk++) {
            uint4 aH = *(const uint4*)(sm + QH_OFF + (kk * 256 + warp * 32 + lane) * 16);
#pragma unroll
            for (int np = 0; np < 4; np++) {
                uint4 bH2 = *(const uint4*)(stK  + (kk * 128 + np * 32 + lane) * 16);
                uint4 bL2 = *(const uint4*)(stKL + (kk * 128 + np * 32 + lane) * 16);
                const unsigned* bh = (const unsigned*)&bH2;
                const unsigned* bl = (const unsigned*)&bL2;
                mma_f16(acc[2*np],     (const unsigned*)&aH, bh);
                mma_f16(acc[2*np],     (const unsigned*)&aH, bl);
                mma_f16(acc[2*np + 1], (const unsigned*)&aH, bh + 2);
                mma_f16(acc[2*np + 1], (const unsigned*)&aH, bl + 2);
            }
        }

#pragma unroll
        for (int nf = 0; nf < 8; nf++)
#pragma unroll
            for (int e = 0; e < 4; e++) acc[nf][e] *= scale;

        if (kb + 63 > qbase + m0) {
#pragma unroll
            for (int nf = 0; nf < 8; nf++) {
                int k0 = kb + nf * 8 + 2 * t;
                if (k0     > row0) acc[nf][0] = -INFINITY;
                if (k0 + 1 > row0) acc[nf][1] = -INFINITY;
                if (k0     > row1) acc[nf][2] = -INFINITY;
                if (k0 + 1 > row1) acc[nf][3] = -INFINITY;
            }
        }

        float mx0 = -INFINITY, mx1 = -INFINITY;
#pragma unroll
        for (int nf = 0; nf < 8; nf++) {
            mx0 = fmaxf(mx0, fmaxf(acc[nf][0], acc[nf][1]));
            mx1 = fmaxf(mx1, fmaxf(acc[nf][2], acc[nf][3]));
        }
        mx0 = fmaxf(mx0, __shfl_xor_sync(0xffffffffu, mx0, 1));
        mx0 = fmaxf(mx0, __shfl_xor_sync(0xffffffffu, mx0, 2));
        mx1 = fmaxf(mx1, __shfl_xor_sync(0xffffffffu, mx1, 1));
        mx1 = fmaxf(mx1, __shfl_xor_sync(0xffffffffu, mx1, 2));

        float mn0 = fmaxf(mr0, mx0);
        float mn1 = fmaxf(mr1, mx1);
        float al0 = __expf(mr0 - mn0);
        float al1 = __expf(mr1 - mn1);
        mr0 = mn0; mr1 = mn1;

        unsigned pH[4][4];
        float s0 = 0.0f, s1 = 0.0f;
#pragma unroll
        for (int nf = 0; nf < 8; nf++) {
            float p00 = __expf(acc[nf][0] - mn0);
            float p01 = __expf(acc[nf][1] - mn0);
            float p10 = __expf(acc[nf][2] - mn1);
            float p11 = __expf(acc[nf][3] - mn1);
            s0 += p00 + p01;
            s1 += p10 + p11;
            int kk2 = nf >> 1;
            int sl  = (nf & 1) << 1;
            pH[kk2][sl]     = pack_h2(p00, p01);
            pH[kk2][sl + 1] = pack_h2(p10, p11);
        }
        s0 += __shfl_xor_sync(0xffffffffu, s0, 1);
        s0 += __shfl_xor_sync(0xffffffffu, s0, 2);
        s1 += __shfl_xor_sync(0xffffffffu, s1, 1);
        s1 += __shfl_xor_sync(0xffffffffu, s1, 2);
        lr0 = lr0 * al0 + s0;
        lr1 = lr1 * al1 + s1;

#pragma unroll
        for (int nf = 0; nf < 16; nf++) {
            ctx[nf][0] *= al0; ctx[nf][1] *= al0;
            ctx[nf][2] *= al1; ctx[nf][3] *= al1;
        }
#pragma unroll
        for (int kk2 = 0; kk2 < 4; kk2++) {
#pragma unroll
            for (int np = 0; np < 8; np++) {
                uint4 vH2 = *(const uint4*)(stV  + (kk2 * 256 + np * 32 + lane) * 16);
                uint4 vL2 = *(const uint4*)(stVL + (kk2 * 256 + np * 32 + lane) * 16);
                const unsigned* vh = (const unsigned*)&vH2;
                const unsigned* vl = (const unsigned*)&vL2;
                mma_f16(ctx[2*np],     pH[kk2], vh);
                mma_f16(ctx[2*np],     pH[kk2], vl);
                mma_f16(ctx[2*np + 1], pH[kk2], vh + 2);
                mma_f16(ctx[2*np + 1], pH[kk2], vl + 2);
            }
        }
        __syncthreads();
    }

    // ---- fused epilogue: stage ctx f32, emit fp16 A-packed g_Ctp ----
    float* cs = (float*)(sm + ST0_OFF);        // 128x132 f32
    {
        float il0 = 1.0f / lr0;
        float il1 = 1.0f / lr1;
        int rl0 = m0 + g;
#pragma unroll
        for (int nf = 0; nf < 16; nf++) {
            int d = nf * 8 + 2 * t;
            *(float2*)(cs + rl0 * 132 + d) =
                make_float2(ctx[nf][0] * il0, ctx[nf][1] * il0);
            *(float2*)(cs + (rl0 + 8) * 132 + d) =
                make_float2(ctx[nf][2] * il1, ctx[nf][3] * il1);
        }
    }
    __syncthreads();

    {
        const int mtile = (b * S_ + qbase) >> 7;
        for (int it = tid; it < 2048; it += 256) {
            int w = it & 1023, kc = it >> 10;
            int ln = w & 31, rf = (w >> 5) & 7, kk = w >> 8;
            int rl = rf * 16 + (ln >> 2);
            int cl = kc * 64 + kk * 16 + 2 * (ln & 3);
            uint4 o = make_uint4(
                pack_h2(cs[rl * 132 + cl],           cs[rl * 132 + cl + 1]),
                pack_h2(cs[(rl + 8) * 132 + cl],     cs[(rl + 8) * 132 + cl + 1]),
                pack_h2(cs[rl * 132 + cl + 8],       cs[rl * 132 + cl + 9]),
                pack_h2(cs[(rl + 8) * 132 + cl + 8], cs[(rl + 8) * 132 + cl + 9]));
            size_t idx = ((size_t)(mtile * 32 + h * 2 + kc)) * 1024 +
                         (kk << 8) + (rf << 5) + ln;
            ((uint4*)g_Ctp)[idx] = o;
        }
    }
}

// ============================================================
// launch
// ============================================================
extern "C" void kernel_launch(void* const* d_in, const int* in_sizes, int n_in,
                              void* d_out, int out_size)
{
    (void)in_sizes; (void)n_in; (void)out_size;
    const float* hidden = (const float*)d_in[0];
    const float* Wq = (const float*)d_in[1];
    const float* bq = (const float*)d_in[2];
    const float* Wk = (const float*)d_in[3];
    const float* bk = (const float*)d_in[4];
    const float* Wv = (const float*)d_in[5];
    const float* bv = (const float*)d_in[6];
    const float* Wo = (const float*)d_in[7];
    float* out = (float*)d_out;

    unsigned *xp, *ctp, *wop;
    cudaGetSymbolAddress((void**)&xp,  g_Xp);
    cudaGetSymbolAddress((void**)&ctp, g_Ctp);
    cudaGetSymbolAddress((void**)&wop, g_Wop);

    cudaFuncSetAttribute(gemm_qkv,
        cudaFuncAttributeMaxDynamicSharedMemorySize, GEMM_SMEM);
    cudaFuncSetAttribute(gemm_v3,
        cudaFuncAttributeMaxDynamicSharedMemorySize, GEMM_SMEM);
    cudaFuncSetAttribute(flash_f16,
        cudaFuncAttributeMaxDynamicSharedMemorySize, FLASH_SMEM);

    const int NPACK = BSR_ * HID_ / 8 + (2048 + 1024 + 1024 + 2048) * HID_ / 4;

    // 1: pack GEMM operands (fp16 fragments)
    pack_all<<<(NPACK + 255) / 256, 256>>>(hidden, Wq, Wk, Wv, Wo);
    // 2: RoPE tables
    rope_table_kernel<<<(S_ * 64 + 255) / 256, 256>>>();
    // 3: fused QKV projections (fp16) + flash fragment epilogues
    gemm_qkv<<<1024, 256, GEMM_SMEM>>>(xp, bq, bk, bv);
    // 4: flash attention (fp16 2-split)  ← profiled launch
    flash_f16<<<dim3(S_ / BQ, NH_, B_), 256, FLASH_SMEM>>>();
    // 5: O projection (fp16) → final output
    gemm_v3<<<dim3(16, 32), 256, GEMM_SMEM>>>(ctp, wop, out, HID_);
}

// round 15
// speedup vs baseline: 1.8295x; 1.1575x over previous
#include <cuda_runtime.h>
#include <cuda_bf16.h>
#include <cuda_fp16.h>
#include <math.h>

#define B_    2
#define S_    2048
#define HID_  2048
#define NH_   16
#define NKV_  8
#define D_    128
#define G_    (NH_/NKV_)
#define BSR_  (B_*S_)          // 4096

// -------- scratch (__device__ globals; no allocations) --------
// flash operands, mma-fragment-packed fp16 (single-precision-pass)
__device__ unsigned g_Qph[BSR_ * NH_ * D_ / 2];     // [rowblk32*NH_][kk8][wr8][ln32] uint4
__device__ unsigned g_Kph[BSR_ * NKV_ * D_ / 2];    // [b2][kvh8][kt32][kk8][np4][ln32] uint4
__device__ unsigned g_Vph[BSR_ * NKV_ * D_ / 2];    // [b2][kvh8][kt32][kk2 4][np8][ln32] uint4
// GEMM operands, fragment-packed FP16
__device__ unsigned g_Xp [BSR_ * HID_ / 2];
__device__ unsigned g_Ctp[BSR_ * NH_ * D_ / 2];
__device__ unsigned g_Wqp[HID_ * NH_ * D_ / 2];
__device__ unsigned g_Wkp[HID_ * NKV_ * D_ / 2];
__device__ unsigned g_Wvp[HID_ * NKV_ * D_ / 2];
__device__ unsigned g_Wop[NH_ * D_ * HID_ / 2];
__device__ float g_cos[S_ * 64];
__device__ float g_sin[S_ * 64];

// ---------------- helpers ----------------
__device__ __forceinline__ void cp16(unsigned dst, const void* src) {
    asm volatile("cp.async.cg.shared.global [%0], [%1], 16;" :: "r"(dst), "l"(src));
}
__device__ __forceinline__ void cp_commit() { asm volatile("cp.async.commit_group;"); }
__device__ __forceinline__ void cp_wait1()  { asm volatile("cp.async.wait_group 1;"); }
__device__ __forceinline__ void cp_wait0()  { asm volatile("cp.async.wait_group 0;"); }

__device__ __forceinline__ unsigned pack_h2(float x, float y) {
    __half2 h;
    h.x = __float2half_rn(x);
    h.y = __float2half_rn(y);
    return *(unsigned*)&h;
}

__device__ __forceinline__ void mma_f16(float* d, const unsigned* a, const unsigned* b) {
    asm volatile(
        "mma.sync.aligned.m16n8k16.row.col.f32.f16.f16.f32 "
        "{%0,%1,%2,%3}, {%4,%5,%6,%7}, {%8,%9}, {%0,%1,%2,%3};\n"
        : "+f"(d[0]), "+f"(d[1]), "+f"(d[2]), "+f"(d[3])
        : "r"(a[0]), "r"(a[1]), "r"(a[2]), "r"(a[3]), "r"(b[0]), "r"(b[1]));
}

__device__ __forceinline__ float rope_elem(const float* sf, int r, int s, int c) {
    if (c < 64)
        return sf[r * 132 + c] * g_cos[s * 64 + c] - sf[r * 132 + c + 64] * g_sin[s * 64 + c];
    int i = c - 64;
    return sf[r * 132 + c] * g_cos[s * 64 + i] + sf[r * 132 + c - 64] * g_sin[s * 64 + i];
}

// ============================================================
// FP16 fragment packing of GEMM operands (validated R14).
// ============================================================
__device__ __forceinline__ void pack_a_one(
    const float* __restrict__ A, unsigned* __restrict__ P, int id)
{
    int w      = id & 1023;
    int chunk  = id >> 10;
    int kchunk = chunk & 31;
    int mtile  = chunk >> 5;
    int lane = w & 31, rf = (w >> 5) & 7, kk = w >> 8;
    int row = mtile * 128 + rf * 16 + (lane >> 2);
    int col = kchunk * 64 + kk * 16 + 2 * (lane & 3);
    const float* a0 = A + (size_t)row * HID_ + col;
    ((uint4*)P)[id] = make_uint4(
        pack_h2(a0[0], a0[1]),
        pack_h2(a0[8 * HID_], a0[8 * HID_ + 1]),
        pack_h2(a0[8], a0[9]),
        pack_h2(a0[8 * HID_ + 8], a0[8 * HID_ + 9]));
}

__device__ __forceinline__ void pack_b_one(
    const float* __restrict__ W, unsigned* __restrict__ P, int N, int id)
{
    int w      = id & 2047;
    int chunk  = id >> 11;
    int kchunk = chunk & 31;
    int ntile  = chunk >> 5;
    int lane = w & 31, nb = (w >> 5) & 15, kk = w >> 9;
    int n = ntile * 128 + nb * 8 + (lane >> 2);
    int c = kchunk * 64 + kk * 16 + 2 * (lane & 3);
    ((uint2*)P)[id] = make_uint2(
        pack_h2(W[(size_t)c * N + n],       W[(size_t)(c + 1) * N + n]),
        pack_h2(W[(size_t)(c + 8) * N + n], W[(size_t)(c + 9) * N + n]));
}

__global__ void pack_all(const float* __restrict__ X,
                         const float* __restrict__ Wq, const float* __restrict__ Wk,
                         const float* __restrict__ Wv, const float* __restrict__ Wo)
{
    const int NA = (BSR_ * HID_) / 8;
    const int NQ = (2048 * HID_) / 4;
    const int NK = (1024 * HID_) / 4;
    int id = blockIdx.x * blockDim.x + threadIdx.x;
    if (id < NA) { pack_a_one(X, g_Xp, id); return; }
    id -= NA;
    if (id < NQ)              { pack_b_one(Wq, g_Wqp, 2048, id); return; }
    if (id < NQ + NK)         { pack_b_one(Wk, g_Wkp, 1024, id - NQ); return; }
    if (id < NQ + 2 * NK)     { pack_b_one(Wv, g_Wvp, 1024, id - NQ - NK); return; }
    if (id < NQ + 2 * NK + NQ)  pack_b_one(Wo, g_Wop, 2048, id - NQ - 2 * NK);
}

// ============================================================
// RoPE tables
// ============================================================
__global__ void rope_table_kernel()
{
    int idx = blockIdx.x * blockDim.x + threadIdx.x;
    if (idx >= S_ * 64) return;
    int s = idx >> 6, i = idx & 63;
    const double NEG_LOG_STEP = -0.2158673524681918;
    double freq = exp((double)i * NEG_LOG_STEP);
    double sd, cd;
    sincos((double)s * freq, &sd, &cd);
    g_cos[idx] = (float)cd;
    g_sin[idx] = (float)sd;
}

// ============================================================
// FP16 GEMM core (validated R14): K-chunk 64, 3-stage cp.async.
// ============================================================
#define CHUNK_BYTES 16384
#define STAGE_BYTES (2 * CHUNK_BYTES)
#define GEMM_SMEM   (3 * STAGE_BYTES)           // 98304

__device__ __forceinline__ void gemm_issue_h(
    unsigned sbase, int stage, const unsigned* __restrict__ Ac,
    const unsigned* __restrict__ Bc, int tid)
{
    unsigned st = sbase + stage * STAGE_BYTES;
#pragma unroll
    for (int p = 0; p < 4; p++) {
        int id = tid + p * 256;
        cp16(st + id * 16,               Ac + id * 4);
        cp16(st + CHUNK_BYTES + id * 16, Bc + id * 4);
    }
    cp_commit();
}

__device__ __forceinline__ void gemm_compute_h(
    const char* st, float acc[4][4][4], int lane, int wm, int wn)
{
    const char* sA = st;
    const char* sB = st + CHUNK_BYTES;
#pragma unroll
    for (int kk = 0; kk < 4; kk++) {
        uint4 a[4]; uint2 b[4];
#pragma unroll
        for (int mf = 0; mf < 4; mf++)
            a[mf] = *(const uint4*)(sA + (((kk * 8 + wm * 4 + mf) * 32) + lane) * 16);
#pragma unroll
        for (int nf = 0; nf < 4; nf++)
            b[nf] = *(const uint2*)(sB + (((kk * 16 + wn * 4 + nf) * 32) + lane) * 8);
#pragma unroll
        for (int mf = 0; mf < 4; mf++)
#pragma unroll
            for (int nf = 0; nf < 4; nf++)
                mma_f16(acc[mf][nf], (const unsigned*)&a[mf], (const unsigned*)&b[nf]);
    }
}

__device__ __forceinline__ void gemm_main_h(
    const unsigned* __restrict__ Ab, const unsigned* __restrict__ Bb,
    float acc[4][4][4], char* smem)
{
    const int tid  = threadIdx.x;
    const int lane = tid & 31;
    const int wm   = (tid >> 5) >> 2;
    const int wn   = (tid >> 5) & 3;
    unsigned sbase = (unsigned)__cvta_generic_to_shared(smem);

    gemm_issue_h(sbase, 0, Ab, Bb, tid);
    gemm_issue_h(sbase, 1, Ab + 4096, Bb + 4096, tid);

    for (int i = 0; i < 32; i++) {
        if (i < 31) cp_wait1(); else cp_wait0();
        __syncthreads();
        if (i + 2 < 32)
            gemm_issue_h(sbase, (i + 2) % 3,
                         Ab + (size_t)(i + 2) * 4096,
                         Bb + (size_t)(i + 2) * 4096, tid);
        gemm_compute_h(smem + (i % 3) * STAGE_BYTES, acc, lane, wm, wn);
    }
}

// ============================================================
// Fused QKV projections; epilogues emit flash fp16 fragments
// (Q A-frag; K/V hi-only paired B-frags).
// ============================================================
__global__ __launch_bounds__(256, 2) void gemm_qkv(
    const unsigned* __restrict__ Ap,
    const float* __restrict__ bq, const float* __restrict__ bk,
    const float* __restrict__ bv)
{
    extern __shared__ char smem[];
    float* sf = (float*)smem;
    const int id = blockIdx.x;
    const unsigned* Bp; const float* bias;
    int bx, by, mode;
    if (id < 512)      { Bp = g_Wqp; bias = bq; bx = id & 15; by = id >> 4; mode = 0; }
    else if (id < 768) { int t = id - 512; Bp = g_Wkp; bias = bk; bx = t & 7; by = t >> 3; mode = 1; }
    else               { int t = id - 768; Bp = g_Wvp; bias = bv; bx = t & 7; by = t >> 3; mode = 2; }

    float acc[4][4][4];
#pragma unroll
    for (int i = 0; i < 4; i++)
#pragma unroll
        for (int j = 0; j < 4; j++)
#pragma unroll
            for (int e = 0; e < 4; e++) acc[i][j][e] = 0.0f;

    gemm_main_h(Ap + (size_t)by * 32 * 4096, Bp + (size_t)bx * 32 * 4096, acc, smem);
    __syncthreads();

    const int tid  = threadIdx.x;
    const int lane = tid & 31;
    const int warp = tid >> 5;
    const int wm = warp >> 2, wn = warp & 3;

    // ---- stage tile (Q/K row-major [r][132]; V transposed [d][132]) ----
#pragma unroll
    for (int mf = 0; mf < 4; mf++) {
        int r = wm * 64 + mf * 16 + (lane >> 2);
#pragma unroll
        for (int nf = 0; nf < 4; nf++) {
            int col = wn * 32 + nf * 8 + 2 * (lane & 3);
            float b0 = bias[bx * 128 + col], b1 = bias[bx * 128 + col + 1];
            float v00 = acc[mf][nf][0] + b0, v01 = acc[mf][nf][1] + b1;
            float v10 = acc[mf][nf][2] + b0, v11 = acc[mf][nf][3] + b1;
            if (mode != 2) {
                *(float2*)(sf + r * 132 + col)       = make_float2(v00, v01);
                *(float2*)(sf + (r + 8) * 132 + col) = make_float2(v10, v11);
            } else {
                sf[col * 132 + r]           = v00;
                sf[(col + 1) * 132 + r]     = v01;
                sf[col * 132 + r + 8]       = v10;
                sf[(col + 1) * 132 + r + 8] = v11;
            }
        }
    }
    __syncthreads();

    if (mode == 0) {
        unsigned* Qh = g_Qph + (size_t)(by * 16 + bx) * 8192;
        for (int it = tid; it < 2048; it += 256) {
            int kk = it >> 8, wr = (it >> 5) & 7, ln = it & 31;
            int r = wr * 16 + (ln >> 2);
            int c = kk * 16 + 2 * (ln & 3);
            int s  = (by * 128 + r) & (S_ - 1);
            int s8 = s + 8;
            ((uint4*)Qh)[it] = make_uint4(
                pack_h2(rope_elem(sf, r, s, c),          rope_elem(sf, r, s, c + 1)),
                pack_h2(rope_elem(sf, r + 8, s8, c),     rope_elem(sf, r + 8, s8, c + 1)),
                pack_h2(rope_elem(sf, r, s, c + 8),      rope_elem(sf, r, s, c + 9)),
                pack_h2(rope_elem(sf, r + 8, s8, c + 8), rope_elem(sf, r + 8, s8, c + 9)));
        }
    } else if (mode == 1) {
        const int bb  = (by * 128) >> 11;
        const int kt0 = ((by * 128) & (S_ - 1)) >> 6;
        size_t kbase4 = ((size_t)((bb * NKV_ + bx) * 32 + kt0)) * 1024;
        for (int it = tid; it < 2048; it += 256) {
            int kt = it >> 10, w = it & 1023;
            int kk = w >> 7, np = (w >> 5) & 3, ln = w & 31;
            int c = kk * 16 + 2 * (ln & 3);
            unsigned hv[4];
#pragma unroll
            for (int p = 0; p < 2; p++) {
                int n = (2 * np + p) * 8 + (ln >> 2);
                int r = kt * 64 + n;
                int s = (by * 128 + r) & (S_ - 1);
                hv[2*p]   = pack_h2(rope_elem(sf, r, s, c),     rope_elem(sf, r, s, c + 1));
                hv[2*p+1] = pack_h2(rope_elem(sf, r, s, c + 8), rope_elem(sf, r, s, c + 9));
            }
            ((uint4*)g_Kph)[kbase4 + kt * 1024 + w] = make_uint4(hv[0], hv[1], hv[2], hv[3]);
        }
    } else {
        const int bb  = (by * 128) >> 11;
        const int kt0 = ((by * 128) & (S_ - 1)) >> 6;
        size_t vbase4 = ((size_t)((bb * NKV_ + bx) * 32 + kt0)) * 1024;
        for (int it = tid; it < 2048; it += 256) {
            int kt = it >> 10, w = it & 1023;
            int kk2 = w >> 8, np = (w >> 5) & 7, ln = w & 31;
            int cl = kk2 * 16 + 2 * (ln & 3);
            int r  = kt * 64 + cl;
            unsigned hv[4];
#pragma unroll
            for (int p = 0; p < 2; p++) {
                int n = (2 * np + p) * 8 + (ln >> 2);
                hv[2*p]   = pack_h2(sf[n * 132 + r],     sf[n * 132 + r + 1]);
                hv[2*p+1] = pack_h2(sf[n * 132 + r + 8], sf[n * 132 + r + 9]);
            }
            ((uint4*)g_Vph)[vbase4 + kt * 1024 + w] = make_uint4(hv[0], hv[1], hv[2], hv[3]);
        }
    }
}

// ============================================================
// O projection GEMM (fp16 core, writes final out)
// ============================================================
__global__ __launch_bounds__(256, 2) void gemm_v3(
    const unsigned* __restrict__ Ap, const unsigned* __restrict__ Bp,
    float* __restrict__ C, int N)
{
    extern __shared__ char smem[];
    float acc[4][4][4];
#pragma unroll
    for (int i = 0; i < 4; i++)
#pragma unroll
        for (int j = 0; j < 4; j++)
#pragma unroll
            for (int e = 0; e < 4; e++) acc[i][j][e] = 0.0f;

    gemm_main_h(Ap + (size_t)blockIdx.y * 32 * 4096,
                Bp + (size_t)blockIdx.x * 32 * 4096, acc, smem);

    const int lane = threadIdx.x & 31;
    const int warp = threadIdx.x >> 5;
    const int wm = warp >> 2, wn = warp & 3;
#pragma unroll
    for (int mf = 0; mf < 4; mf++) {
        int row = blockIdx.y * 128 + wm * 64 + mf * 16 + (lane >> 2);
#pragma unroll
        for (int nf = 0; nf < 4; nf++) {
            int col = blockIdx.x * 128 + wn * 32 + nf * 8 + 2 * (lane & 3);
            *(float2*)&C[(size_t)row * N + col] =
                make_float2(acc[mf][nf][0], acc[mf][nf][1]);
            *(float2*)&C[(size_t)(row + 8) * N + col] =
                make_float2(acc[mf][nf][2], acc[mf][nf][3]);
        }
    }
}

// ============================================================
// Flash attention: single-pass fp16 (Q·K, P·V), paired frags,
// register softmax, fp16 A-pack ctx epilogue.
// smem: QH 32K | 2 stages x (Kh16K Vh16K) = 98304
// ============================================================
#define BQ 128
#define QH_OFF 0
#define ST0_OFF 32768
#define FSTAGE 32768
#define FLASH_SMEM (ST0_OFF + 2 * FSTAGE)     // 98304

__device__ __forceinline__ void flash_issue(
    unsigned sbase, int stage, size_t base_u, int tid)
{
    unsigned st = sbase + ST0_OFF + stage * FSTAGE;
#pragma unroll
    for (int p = 0; p < 4; p++) {
        int id = tid + p * 256;
        cp16(st + id * 16,         g_Kph + base_u + id * 4);
        cp16(st + 16384 + id * 16, g_Vph + base_u + id * 4);
    }
    cp_commit();
}

__global__ __launch_bounds__(256, 1) void flash_f16()
{
    extern __shared__ char sm[];
    const int tid  = threadIdx.x;
    const int lane = tid & 31;
    const int warp = tid >> 5;
    const int qtile = (gridDim.x - 1) - blockIdx.x;
    const int h    = blockIdx.y;
    const int b    = blockIdx.z;
    const int kvh  = h / G_;
    const int qbase = qtile * BQ;
    const float scale = 0.08838834764831845f;
    const int g = lane >> 2;
    const int t = lane & 3;
    const int m0 = warp * 16;
    unsigned sbase = (unsigned)__cvta_generic_to_shared(sm);

    const size_t kvstep = 4096;
    const size_t kvb0 = ((size_t)(b * NKV_ + kvh) * 32) * kvstep;

    flash_issue(sbase, 0, kvb0, tid);

    {
        const int mq = (b * S_ + qbase) >> 7;
        const uint4* qh = (const uint4*)g_Qph + (size_t)(mq * 16 + h) * 2048;
        for (int it = tid; it < 2048; it += 256)
            *(uint4*)(sm + QH_OFF + it * 16) = qh[it];
    }

    float ctx[16][4];
#pragma unroll
    for (int i = 0; i < 16; i++)
#pragma unroll
        for (int e = 0; e < 4; e++) ctx[i][e] = 0.0f;
    float mr0 = -INFINITY, mr1 = -INFINITY, lr0 = 0.0f, lr1 = 0.0f;

    const int row0 = qbase + m0 + g;
    const int row1 = row0 + 8;
    const int ntile = 2 * qtile + 2;

    for (int j = 0; j < ntile; j++) {
        const int kb = j * 64;
        if (j + 1 < ntile) {
            flash_issue(sbase, (j + 1) & 1, kvb0 + (size_t)(j + 1) * kvstep, tid);
            cp_wait1();
        } else {
            cp_wait0();
        }
        __syncthreads();

        const char* stg = sm + ST0_OFF + (j & 1) * FSTAGE;
        const char* stK = stg;
        const char* stV = stg + 16384;

        float acc[8][4];
#pragma unroll
        for (int nf = 0; nf < 8; nf++)
#pragma unroll
            for (int e = 0; e < 4; e++) acc[nf][e] = 0.0f;

        // ---- QK: qH · kH ----
#pragma unroll
        for (int kk = 0; kk < 8; kk++) {
            uint4 aH = *(const uint4*)(sm + QH_OFF + (kk * 256 + warp * 32 + lane) * 16);
#pragma unroll
            for (int np = 0; np < 4; np++) {
                uint4 bH2 = *(const uint4*)(stK + (kk * 128 + np * 32 + lane) * 16);
                const unsigned* bh = (const unsigned*)&bH2;
                mma_f16(acc[2*np],     (const unsigned*)&aH, bh);
                mma_f16(acc[2*np + 1], (const unsigned*)&aH, bh + 2);
            }
        }

#pragma unroll
        for (int nf = 0; nf < 8; nf++)
#pragma unroll
            for (int e = 0; e < 4; e++) acc[nf][e] *= scale;

        if (kb + 63 > qbase + m0) {
#pragma unroll
            for (int nf = 0; nf < 8; nf++) {
                int k0 = kb + nf * 8 + 2 * t;
                if (k0     > row0) acc[nf][0] = -INFINITY;
                if (k0 + 1 > row0) acc[nf][1] = -INFINITY;
                if (k0     > row1) acc[nf][2] = -INFINITY;
                if (k0 + 1 > row1) acc[nf][3] = -INFINITY;
            }
        }

        float mx0 = -INFINITY, mx1 = -INFINITY;
#pragma unroll
        for (int nf = 0; nf < 8; nf++) {
            mx0 = fmaxf(mx0, fmaxf(acc[nf][0], acc[nf][1]));
            mx1 = fmaxf(mx1, fmaxf(acc[nf][2], acc[nf][3]));
        }
        mx0 = fmaxf(mx0, __shfl_xor_sync(0xffffffffu, mx0, 1));
        mx0 = fmaxf(mx0, __shfl_xor_sync(0xffffffffu, mx0, 2));
        mx1 = fmaxf(mx1, __shfl_xor_sync(0xffffffffu, mx1, 1));
        mx1 = fmaxf(mx1, __shfl_xor_sync(0xffffffffu, mx1, 2));

        float mn0 = fmaxf(mr0, mx0);
        float mn1 = fmaxf(mr1, mx1);
        float al0 = __expf(mr0 - mn0);
        float al1 = __expf(mr1 - mn1);
        mr0 = mn0; mr1 = mn1;

        unsigned pH[4][4];
        float s0 = 0.0f, s1 = 0.0f;
#pragma unroll
        for (int nf = 0; nf < 8; nf++) {
            float p00 = __expf(acc[nf][0] - mn0);
            float p01 = __expf(acc[nf][1] - mn0);
            float p10 = __expf(acc[nf][2] - mn1);
            float p11 = __expf(acc[nf][3] - mn1);
            s0 += p00 + p01;
            s1 += p10 + p11;
            int kk2 = nf >> 1;
            int sl  = (nf & 1) << 1;
            pH[kk2][sl]     = pack_h2(p00, p01);
            pH[kk2][sl + 1] = pack_h2(p10, p11);
        }
        s0 += __shfl_xor_sync(0xffffffffu, s0, 1);
        s0 += __shfl_xor_sync(0xffffffffu, s0, 2);
        s1 += __shfl_xor_sync(0xffffffffu, s1, 1);
        s1 += __shfl_xor_sync(0xffffffffu, s1, 2);
        lr0 = lr0 * al0 + s0;
        lr1 = lr1 * al1 + s1;

#pragma unroll
        for (int nf = 0; nf < 16; nf++) {
            ctx[nf][0] *= al0; ctx[nf][1] *= al0;
            ctx[nf][2] *= al1; ctx[nf][3] *= al1;
        }
        // ---- PV: pH · vH ----
#pragma unroll
        for (int kk2 = 0; kk2 < 4; kk2++) {
#pragma unroll
            for (int np = 0; np < 8; np++) {
                uint4 vH2 = *(const uint4*)(stV + (kk2 * 256 + np * 32 + lane) * 16);
                const unsigned* vh = (const unsigned*)&vH2;
                mma_f16(ctx[2*np],     pH[kk2], vh);
                mma_f16(ctx[2*np + 1], pH[kk2], vh + 2);
            }
        }
        __syncthreads();
    }

    // ---- fused epilogue: stage ctx f32 (at Q area), emit fp16 A-pack ----
    float* cs = (float*)sm;                    // 128x132 f32 = 67.6KB <= 96KB
    __syncthreads();
    {
        float il0 = 1.0f / lr0;
        float il1 = 1.0f / lr1;
        int rl0 = m0 + g;
#pragma unroll
        for (int nf = 0; nf < 16; nf++) {
            int d = nf * 8 + 2 * t;
            *(float2*)(cs + rl0 * 132 + d) =
                make_float2(ctx[nf][0] * il0, ctx[nf][1] * il0);
            *(float2*)(cs + (rl0 + 8) * 132 + d) =
                make_float2(ctx[nf][2] * il1, ctx[nf][3] * il1);
        }
    }
    __syncthreads();

    {
        const int mtile = (b * S_ + qbase) >> 7;
        for (int it = tid; it < 2048; it += 256) {
            int w = it & 1023, kc = it >> 10;
            int ln = w & 31, rf = (w >> 5) & 7, kk = w >> 8;
            int rl = rf * 16 + (ln >> 2);
            int cl = kc * 64 + kk * 16 + 2 * (ln & 3);
            uint4 o = make_uint4(
                pack_h2(cs[rl * 132 + cl],           cs[rl * 132 + cl + 1]),
                pack_h2(cs[(rl + 8) * 132 + cl],     cs[(rl + 8) * 132 + cl + 1]),
                pack_h2(cs[rl * 132 + cl + 8],       cs[rl * 132 + cl + 9]),
                pack_h2(cs[(rl + 8) * 132 + cl + 8], cs[(rl + 8) * 132 + cl + 9]));
            size_t idx = ((size_t)(mtile * 32 + h * 2 + kc)) * 1024 +
                         (kk << 8) + (rf << 5) + ln;
            ((uint4*)g_Ctp)[idx] = o;
        }
    }
}

// ============================================================
// launch
// ============================================================
extern "C" void kernel_launch(void* const* d_in, const int* in_sizes, int n_in,
                              void* d_out, int out_size)
{
    (void)in_sizes; (void)n_in; (void)out_size;
    const float* hidden = (const float*)d_in[0];
    const float* Wq = (const float*)d_in[1];
    const float* bq = (const float*)d_in[2];
    const float* Wk = (const float*)d_in[3];
    const float* bk = (const float*)d_in[4];
    const float* Wv = (const float*)d_in[5];
    const float* bv = (const float*)d_in[6];
    const float* Wo = (const float*)d_in[7];
    float* out = (float*)d_out;

    unsigned *xp, *ctp, *wop;
    cudaGetSymbolAddress((void**)&xp,  g_Xp);
    cudaGetSymbolAddress((void**)&ctp, g_Ctp);
    cudaGetSymbolAddress((void**)&wop, g_Wop);

    cudaFuncSetAttribute(gemm_qkv,
        cudaFuncAttributeMaxDynamicSharedMemorySize, GEMM_SMEM);
    cudaFuncSetAttribute(gemm_v3,
        cudaFuncAttributeMaxDynamicSharedMemorySize, GEMM_SMEM);
    cudaFuncSetAttribute(flash_f16,
        cudaFuncAttributeMaxDynamicSharedMemorySize, FLASH_SMEM);

    const int NPACK = BSR_ * HID_ / 8 + (2048 + 1024 + 1024 + 2048) * HID_ / 4;

    // 1: pack GEMM operands (fp16 fragments)
    pack_all<<<(NPACK + 255) / 256, 256>>>(hidden, Wq, Wk, Wv, Wo);
    // 2: RoPE tables
    rope_table_kernel<<<(S_ * 64 + 255) / 256, 256>>>();
    // 3: fused QKV projections + flash fragment epilogues
    gemm_qkv<<<1024, 256, GEMM_SMEM>>>(xp, bq, bk, bv);
    // 4: flash attention (single-pass fp16)  ← profiled launch
    flash_f16<<<dim3(S_ / BQ, NH_, B_), 256, FLASH_SMEM>>>();
    // 5: O projection → final output
    gemm_v3<<<dim3(16, 32), 256, GEMM_SMEM>>>(ctp, wop, out, HID_);
}

// round 16
// speedup vs baseline: 1.9918x; 1.0887x over previous
#include <cuda_runtime.h>
#include <cuda_bf16.h>
#include <cuda_fp16.h>
#include <math.h>

#define B_    2
#define S_    2048
#define HID_  2048
#define NH_   16
#define NKV_  8
#define D_    128
#define G_    (NH_/NKV_)
#define BSR_  (B_*S_)          // 4096

// -------- scratch (__device__ globals; no allocations) --------
// flash operands, mma-fragment-packed fp16 (single-pass)
__device__ unsigned g_Qph[BSR_ * NH_ * D_ / 2];     // [rowblk32*NH_][kk8][wr8][ln32] uint4
__device__ unsigned g_Kph[BSR_ * NKV_ * D_ / 2];    // [b2][kvh8][kt32][kk8][np4][ln32] uint4
__device__ unsigned g_Vph[BSR_ * NKV_ * D_ / 2];    // [b2][kvh8][kt32][kk2 4][np8][ln32] uint4
// GEMM operands, fragment-packed FP16 (B now PAIRED: uint4 per 2 nf)
__device__ unsigned g_Xp [BSR_ * HID_ / 2];         // A: [mtile][kc32][kk4][rf8][ln32] uint4
__device__ unsigned g_Ctp[BSR_ * NH_ * D_ / 2];
__device__ unsigned g_Wqp[HID_ * NH_ * D_ / 2];     // B: [ntile][kc32][kk4][np8][ln32] uint4
__device__ unsigned g_Wkp[HID_ * NKV_ * D_ / 2];
__device__ unsigned g_Wvp[HID_ * NKV_ * D_ / 2];
__device__ unsigned g_Wop[NH_ * D_ * HID_ / 2];
__device__ float g_cos[S_ * 64];
__device__ float g_sin[S_ * 64];

// ---------------- helpers ----------------
__device__ __forceinline__ void cp16(unsigned dst, const void* src) {
    asm volatile("cp.async.cg.shared.global [%0], [%1], 16;" :: "r"(dst), "l"(src));
}
__device__ __forceinline__ void cp_commit() { asm volatile("cp.async.commit_group;"); }
__device__ __forceinline__ void cp_wait1()  { asm volatile("cp.async.wait_group 1;"); }
__device__ __forceinline__ void cp_wait0()  { asm volatile("cp.async.wait_group 0;"); }

__device__ __forceinline__ unsigned pack_h2(float x, float y) {
    __half2 h;
    h.x = __float2half_rn(x);
    h.y = __float2half_rn(y);
    return *(unsigned*)&h;
}

__device__ __forceinline__ void mma_f16(float* d, const unsigned* a, const unsigned* b) {
    asm volatile(
        "mma.sync.aligned.m16n8k16.row.col.f32.f16.f16.f32 "
        "{%0,%1,%2,%3}, {%4,%5,%6,%7}, {%8,%9}, {%0,%1,%2,%3};\n"
        : "+f"(d[0]), "+f"(d[1]), "+f"(d[2]), "+f"(d[3])
        : "r"(a[0]), "r"(a[1]), "r"(a[2]), "r"(a[3]), "r"(b[0]), "r"(b[1]));
}

__device__ __forceinline__ float rope_elem(const float* sf, int r, int s, int c) {
    if (c < 64)
        return sf[r * 132 + c] * g_cos[s * 64 + c] - sf[r * 132 + c + 64] * g_sin[s * 64 + c];
    int i = c - 64;
    return sf[r * 132 + c] * g_cos[s * 64 + i] + sf[r * 132 + c - 64] * g_sin[s * 64 + i];
}

// ============================================================
// FP16 fragment packing. A unchanged (R14). B now paired:
// uint4 = {b0(n),b1(n), b0(n+8),b1(n+8)},
//   n = ntile*128 + 2*np*8 + (ln>>2), c = kc*64 + kk*16 + 2(ln&3)
// Chunk: A 1024 uint4 = 16KB, B 1024 uint4 = 16KB.
// RoPE tables folded into the same launch.
// ============================================================
__device__ __forceinline__ void pack_a_one(
    const float* __restrict__ A, unsigned* __restrict__ P, int id)
{
    int w      = id & 1023;
    int chunk  = id >> 10;
    int kchunk = chunk & 31;
    int mtile  = chunk >> 5;
    int lane = w & 31, rf = (w >> 5) & 7, kk = w >> 8;
    int row = mtile * 128 + rf * 16 + (lane >> 2);
    int col = kchunk * 64 + kk * 16 + 2 * (lane & 3);
    const float* a0 = A + (size_t)row * HID_ + col;
    ((uint4*)P)[id] = make_uint4(
        pack_h2(a0[0], a0[1]),
        pack_h2(a0[8 * HID_], a0[8 * HID_ + 1]),
        pack_h2(a0[8], a0[9]),
        pack_h2(a0[8 * HID_ + 8], a0[8 * HID_ + 9]));
}

__device__ __forceinline__ void pack_b_one(
    const float* __restrict__ W, unsigned* __restrict__ P, int N, int id)
{
    int w      = id & 1023;
    int chunk  = id >> 10;
    int kchunk = chunk & 31;
    int ntile  = chunk >> 5;
    int lane = w & 31, np = (w >> 5) & 7, kk = w >> 8;
    int n0 = ntile * 128 + 2 * np * 8 + (lane >> 2);
    int n1 = n0 + 8;
    int c  = kchunk * 64 + kk * 16 + 2 * (lane & 3);
    ((uint4*)P)[id] = make_uint4(
        pack_h2(W[(size_t)c * N + n0],       W[(size_t)(c + 1) * N + n0]),
        pack_h2(W[(size_t)(c + 8) * N + n0], W[(size_t)(c + 9) * N + n0]),
        pack_h2(W[(size_t)c * N + n1],       W[(size_t)(c + 1) * N + n1]),
        pack_h2(W[(size_t)(c + 8) * N + n1], W[(size_t)(c + 9) * N + n1]));
}

__global__ void pack_all(const float* __restrict__ X,
                         const float* __restrict__ Wq, const float* __restrict__ Wk,
                         const float* __restrict__ Wv, const float* __restrict__ Wo)
{
    const int NA = (BSR_ * HID_) / 8;       // A uint4 jobs
    const int NQ = (2048 * HID_) / 8;       // B uint4 jobs
    const int NK = (1024 * HID_) / 8;
    int id = blockIdx.x * blockDim.x + threadIdx.x;
    if (id < NA) { pack_a_one(X, g_Xp, id); return; }
    id -= NA;
    if (id < NQ)               { pack_b_one(Wq, g_Wqp, 2048, id); return; }
    if (id < NQ + NK)          { pack_b_one(Wk, g_Wkp, 1024, id - NQ); return; }
    if (id < NQ + 2 * NK)      { pack_b_one(Wv, g_Wvp, 1024, id - NQ - NK); return; }
    if (id < NQ + 2 * NK + NQ) { pack_b_one(Wo, g_Wop, 2048, id - NQ - 2 * NK); return; }
    id -= NQ + 2 * NK + NQ;
    if (id < S_ * 64) {
        int s = id >> 6, i = id & 63;
        const double NEG_LOG_STEP = -0.2158673524681918;
        double freq = exp((double)i * NEG_LOG_STEP);
        double sd, cd;
        sincos((double)s * freq, &sd, &cd);
        g_cos[id] = (float)cd;
        g_sin[id] = (float)sd;
    }
}

// ============================================================
// FP16 GEMM core: K-chunk 64, 3-stage cp.async, paired-B LDS.128.
// ============================================================
#define CHUNK_BYTES 16384
#define STAGE_BYTES (2 * CHUNK_BYTES)
#define GEMM_SMEM   (3 * STAGE_BYTES)           // 98304

__device__ __forceinline__ void gemm_issue_h(
    unsigned sbase, int stage, const unsigned* __restrict__ Ac,
    const unsigned* __restrict__ Bc, int tid)
{
    unsigned st = sbase + stage * STAGE_BYTES;
#pragma unroll
    for (int p = 0; p < 4; p++) {
        int id = tid + p * 256;
        cp16(st + id * 16,               Ac + id * 4);
        cp16(st + CHUNK_BYTES + id * 16, Bc + id * 4);
    }
    cp_commit();
}

__device__ __forceinline__ void gemm_compute_h(
    const char* st, float acc[4][4][4], int lane, int wm, int wn)
{
    const char* sA = st;
    const char* sB = st + CHUNK_BYTES;
#pragma unroll
    for (int kk = 0; kk < 4; kk++) {
        uint4 a[4];
#pragma unroll
        for (int mf = 0; mf < 4; mf++)
            a[mf] = *(const uint4*)(sA + (((kk * 8 + wm * 4 + mf) * 32) + lane) * 16);
        uint4 b2[2];
#pragma unroll
        for (int p = 0; p < 2; p++)
            b2[p] = *(const uint4*)(sB + (((kk * 8 + wn * 2 + p) * 32) + lane) * 16);
#pragma unroll
        for (int mf = 0; mf < 4; mf++) {
#pragma unroll
            for (int p = 0; p < 2; p++) {
                const unsigned* bp = (const unsigned*)&b2[p];
                mma_f16(acc[mf][2 * p],     (const unsigned*)&a[mf], bp);
                mma_f16(acc[mf][2 * p + 1], (const unsigned*)&a[mf], bp + 2);
            }
        }
    }
}

__device__ __forceinline__ void gemm_main_h(
    const unsigned* __restrict__ Ab, const unsigned* __restrict__ Bb,
    float acc[4][4][4], char* smem)
{
    const int tid  = threadIdx.x;
    const int lane = tid & 31;
    const int wm   = (tid >> 5) >> 2;
    const int wn   = (tid >> 5) & 3;
    unsigned sbase = (unsigned)__cvta_generic_to_shared(smem);

    gemm_issue_h(sbase, 0, Ab, Bb, tid);
    gemm_issue_h(sbase, 1, Ab + 4096, Bb + 4096, tid);

    for (int i = 0; i < 32; i++) {
        if (i < 31) cp_wait1(); else cp_wait0();
        __syncthreads();
        if (i + 2 < 32)
            gemm_issue_h(sbase, (i + 2) % 3,
                         Ab + (size_t)(i + 2) * 4096,
                         Bb + (size_t)(i + 2) * 4096, tid);
        gemm_compute_h(smem + (i % 3) * STAGE_BYTES, acc, lane, wm, wn);
    }
}

// ============================================================
// Fused QKV projections; epilogues emit flash fp16 fragments.
// nf local mapping in epilogue: col = wn*32 + nf*8 (unchanged —
// acc[mf][2p+q] corresponds to n = wn*32 + (2p+q)*8, same as before).
// ============================================================
__global__ __launch_bounds__(256, 2) void gemm_qkv(
    const unsigned* __restrict__ Ap,
    const float* __restrict__ bq, const float* __restrict__ bk,
    const float* __restrict__ bv)
{
    extern __shared__ char smem[];
    float* sf = (float*)smem;
    const int id = blockIdx.x;
    const unsigned* Bp; const float* bias;
    int bx, by, mode;
    if (id < 512)      { Bp = g_Wqp; bias = bq; bx = id & 15; by = id >> 4; mode = 0; }
    else if (id < 768) { int t = id - 512; Bp = g_Wkp; bias = bk; bx = t & 7; by = t >> 3; mode = 1; }
    else               { int t = id - 768; Bp = g_Wvp; bias = bv; bx = t & 7; by = t >> 3; mode = 2; }

    float acc[4][4][4];
#pragma unroll
    for (int i = 0; i < 4; i++)
#pragma unroll
        for (int j = 0; j < 4; j++)
#pragma unroll
            for (int e = 0; e < 4; e++) acc[i][j][e] = 0.0f;

    gemm_main_h(Ap + (size_t)by * 32 * 4096, Bp + (size_t)bx * 32 * 4096, acc, smem);
    __syncthreads();

    const int tid  = threadIdx.x;
    const int lane = tid & 31;
    const int warp = tid >> 5;
    const int wm = warp >> 2, wn = warp & 3;

#pragma unroll
    for (int mf = 0; mf < 4; mf++) {
        int r = wm * 64 + mf * 16 + (lane >> 2);
#pragma unroll
        for (int nf = 0; nf < 4; nf++) {
            int col = wn * 32 + nf * 8 + 2 * (lane & 3);
            float b0 = bias[bx * 128 + col], b1 = bias[bx * 128 + col + 1];
            float v00 = acc[mf][nf][0] + b0, v01 = acc[mf][nf][1] + b1;
            float v10 = acc[mf][nf][2] + b0, v11 = acc[mf][nf][3] + b1;
            if (mode != 2) {
                *(float2*)(sf + r * 132 + col)       = make_float2(v00, v01);
                *(float2*)(sf + (r + 8) * 132 + col) = make_float2(v10, v11);
            } else {
                sf[col * 132 + r]           = v00;
                sf[(col + 1) * 132 + r]     = v01;
                sf[col * 132 + r + 8]       = v10;
                sf[(col + 1) * 132 + r + 8] = v11;
            }
        }
    }
    __syncthreads();

    if (mode == 0) {
        unsigned* Qh = g_Qph + (size_t)(by * 16 + bx) * 8192;
        for (int it = tid; it < 2048; it += 256) {
            int kk = it >> 8, wr = (it >> 5) & 7, ln = it & 31;
            int r = wr * 16 + (ln >> 2);
            int c = kk * 16 + 2 * (ln & 3);
            int s  = (by * 128 + r) & (S_ - 1);
            int s8 = s + 8;
            ((uint4*)Qh)[it] = make_uint4(
                pack_h2(rope_elem(sf, r, s, c),          rope_elem(sf, r, s, c + 1)),
                pack_h2(rope_elem(sf, r + 8, s8, c),     rope_elem(sf, r + 8, s8, c + 1)),
                pack_h2(rope_elem(sf, r, s, c + 8),      rope_elem(sf, r, s, c + 9)),
                pack_h2(rope_elem(sf, r + 8, s8, c + 8), rope_elem(sf, r + 8, s8, c + 9)));
        }
    } else if (mode == 1) {
        const int bb  = (by * 128) >> 11;
        const int kt0 = ((by * 128) & (S_ - 1)) >> 6;
        size_t kbase4 = ((size_t)((bb * NKV_ + bx) * 32 + kt0)) * 1024;
        for (int it = tid; it < 2048; it += 256) {
            int kt = it >> 10, w = it & 1023;
            int kk = w >> 7, np = (w >> 5) & 3, ln = w & 31;
            int c = kk * 16 + 2 * (ln & 3);
            unsigned hv[4];
#pragma unroll
            for (int p = 0; p < 2; p++) {
                int n = (2 * np + p) * 8 + (ln >> 2);
                int r = kt * 64 + n;
                int s = (by * 128 + r) & (S_ - 1);
                hv[2*p]   = pack_h2(rope_elem(sf, r, s, c),     rope_elem(sf, r, s, c + 1));
                hv[2*p+1] = pack_h2(rope_elem(sf, r, s, c + 8), rope_elem(sf, r, s, c + 9));
            }
            ((uint4*)g_Kph)[kbase4 + kt * 1024 + w] = make_uint4(hv[0], hv[1], hv[2], hv[3]);
        }
    } else {
        const int bb  = (by * 128) >> 11;
        const int kt0 = ((by * 128) & (S_ - 1)) >> 6;
        size_t vbase4 = ((size_t)((bb * NKV_ + bx) * 32 + kt0)) * 1024;
        for (int it = tid; it < 2048; it += 256) {
            int kt = it >> 10, w = it & 1023;
            int kk2 = w >> 8, np = (w >> 5) & 7, ln = w & 31;
            int cl = kk2 * 16 + 2 * (ln & 3);
            int r  = kt * 64 + cl;
            unsigned hv[4];
#pragma unroll
            for (int p = 0; p < 2; p++) {
                int n = (2 * np + p) * 8 + (ln >> 2);
                hv[2*p]   = pack_h2(sf[n * 132 + r],     sf[n * 132 + r + 1]);
                hv[2*p+1] = pack_h2(sf[n * 132 + r + 8], sf[n * 132 + r + 9]);
            }
            ((uint4*)g_Vph)[vbase4 + kt * 1024 + w] = make_uint4(hv[0], hv[1], hv[2], hv[3]);
        }
    }
}

// ============================================================
// O projection GEMM
// ============================================================
__global__ __launch_bounds__(256, 2) void gemm_v3(
    const unsigned* __restrict__ Ap, const unsigned* __restrict__ Bp,
    float* __restrict__ C, int N)
{
    extern __shared__ char smem[];
    float acc[4][4][4];
#pragma unroll
    for (int i = 0; i < 4; i++)
#pragma unroll
        for (int j = 0; j < 4; j++)
#pragma unroll
            for (int e = 0; e < 4; e++) acc[i][j][e] = 0.0f;

    gemm_main_h(Ap + (size_t)blockIdx.y * 32 * 4096,
                Bp + (size_t)blockIdx.x * 32 * 4096, acc, smem);

    const int lane = threadIdx.x & 31;
    const int warp = threadIdx.x >> 5;
    const int wm = warp >> 2, wn = warp & 3;
#pragma unroll
    for (int mf = 0; mf < 4; mf++) {
        int row = blockIdx.y * 128 + wm * 64 + mf * 16 + (lane >> 2);
#pragma unroll
        for (int nf = 0; nf < 4; nf++) {
            int col = blockIdx.x * 128 + wn * 32 + nf * 8 + 2 * (lane & 3);
            *(float2*)&C[(size_t)row * N + col] =
                make_float2(acc[mf][nf][0], acc[mf][nf][1]);
            *(float2*)&C[(size_t)(row + 8) * N + col] =
                make_float2(acc[mf][nf][2], acc[mf][nf][3]);
        }
    }
}

// ============================================================
// Flash attention: single-pass fp16, Q fragments in REGISTERS
// (loaded once from gmem), K/V double-buffered in smem.
// smem: 2 stages x (Kh16K Vh16K) = 64KB; ctx staging reuses it.
// ============================================================
#define BQ 128
#define FSTAGE 32768
#define FLASH_SMEM 67584          // max(2*FSTAGE=65536, ctx 128*132*4=67584)

__device__ __forceinline__ void flash_issue(
    unsigned sbase, int stage, size_t base_u, int tid)
{
    unsigned st = sbase + stage * FSTAGE;
#pragma unroll
    for (int p = 0; p < 4; p++) {
        int id = tid + p * 256;
        cp16(st + id * 16,         g_Kph + base_u + id * 4);
        cp16(st + 16384 + id * 16, g_Vph + base_u + id * 4);
    }
    cp_commit();
}

__global__ __launch_bounds__(256, 1) void flash_f16()
{
    extern __shared__ char sm[];
    const int tid  = threadIdx.x;
    const int lane = tid & 31;
    const int warp = tid >> 5;
    const int qtile = (gridDim.x - 1) - blockIdx.x;
    const int h    = blockIdx.y;
    const int b    = blockIdx.z;
    const int kvh  = h / G_;
    const int qbase = qtile * BQ;
    const float scale = 0.08838834764831845f;
    const int g = lane >> 2;
    const int t = lane & 3;
    const int m0 = warp * 16;
    unsigned sbase = (unsigned)__cvta_generic_to_shared(sm);

    const size_t kvstep = 4096;
    const size_t kvb0 = ((size_t)(b * NKV_ + kvh) * 32) * kvstep;

    flash_issue(sbase, 0, kvb0, tid);

    // Q fragments straight into registers (one coalesced LDG.128 burst)
    uint4 aQ[8];
    {
        const int mq = (b * S_ + qbase) >> 7;
        const uint4* qh = (const uint4*)g_Qph + (size_t)(mq * 16 + h) * 2048;
#pragma unroll
        for (int kk = 0; kk < 8; kk++)
            aQ[kk] = qh[kk * 256 + warp * 32 + lane];
    }

    float ctx[16][4];
#pragma unroll
    for (int i = 0; i < 16; i++)
#pragma unroll
        for (int e = 0; e < 4; e++) ctx[i][e] = 0.0f;
    float mr0 = -INFINITY, mr1 = -INFINITY, lr0 = 0.0f, lr1 = 0.0f;

    const int row0 = qbase + m0 + g;
    const int row1 = row0 + 8;
    const int ntile = 2 * qtile + 2;

    for (int j = 0; j < ntile; j++) {
        const int kb = j * 64;
        if (j + 1 < ntile) {
            flash_issue(sbase, (j + 1) & 1, kvb0 + (size_t)(j + 1) * kvstep, tid);
            cp_wait1();
        } else {
            cp_wait0();
        }
        __syncthreads();

        const char* stg = sm + (j & 1) * FSTAGE;
        const char* stK = stg;
        const char* stV = stg + 16384;

        float acc[8][4];
#pragma unroll
        for (int nf = 0; nf < 8; nf++)
#pragma unroll
            for (int e = 0; e < 4; e++) acc[nf][e] = 0.0f;

        // ---- QK: qH · kH (Q from registers) ----
#pragma unroll
        for (int kk = 0; kk < 8; kk++) {
#pragma unroll
            for (int np = 0; np < 4; np++) {
                uint4 bH2 = *(const uint4*)(stK + (kk * 128 + np * 32 + lane) * 16);
                const unsigned* bh = (const unsigned*)&bH2;
                mma_f16(acc[2*np],     (const unsigned*)&aQ[kk], bh);
                mma_f16(acc[2*np + 1], (const unsigned*)&aQ[kk], bh + 2);
            }
        }

#pragma unroll
        for (int nf = 0; nf < 8; nf++)
#pragma unroll
            for (int e = 0; e < 4; e++) acc[nf][e] *= scale;

        if (kb + 63 > qbase + m0) {
#pragma unroll
            for (int nf = 0; nf < 8; nf++) {
                int k0 = kb + nf * 8 + 2 * t;
                if (k0     > row0) acc[nf][0] = -INFINITY;
                if (k0 + 1 > row0) acc[nf][1] = -INFINITY;
                if (k0     > row1) acc[nf][2] = -INFINITY;
                if (k0 + 1 > row1) acc[nf][3] = -INFINITY;
            }
        }

        float mx0 = -INFINITY, mx1 = -INFINITY;
#pragma unroll
        for (int nf = 0; nf < 8; nf++) {
            mx0 = fmaxf(mx0, fmaxf(acc[nf][0], acc[nf][1]));
            mx1 = fmaxf(mx1, fmaxf(acc[nf][2], acc[nf][3]));
        }
        mx0 = fmaxf(mx0, __shfl_xor_sync(0xffffffffu, mx0, 1));
        mx0 = fmaxf(mx0, __shfl_xor_sync(0xffffffffu, mx0, 2));
        mx1 = fmaxf(mx1, __shfl_xor_sync(0xffffffffu, mx1, 1));
        mx1 = fmaxf(mx1, __shfl_xor_sync(0xffffffffu, mx1, 2));

        float mn0 = fmaxf(mr0, mx0);
        float mn1 = fmaxf(mr1, mx1);
        float al0 = __expf(mr0 - mn0);
        float al1 = __expf(mr1 - mn1);
        mr0 = mn0; mr1 = mn1;

        unsigned pH[4][4];
        float s0 = 0.0f, s1 = 0.0f;
#pragma unroll
        for (int nf = 0; nf < 8; nf++) {
            float p00 = __expf(acc[nf][0] - mn0);
            float p01 = __expf(acc[nf][1] - mn0);
            float p10 = __expf(acc[nf][2] - mn1);
            float p11 = __expf(acc[nf][3] - mn1);
            s0 += p00 + p01;
            s1 += p10 + p11;
            int kk2 = nf >> 1;
            int sl  = (nf & 1) << 1;
            pH[kk2][sl]     = pack_h2(p00, p01);
            pH[kk2][sl + 1] = pack_h2(p10, p11);
        }
        s0 += __shfl_xor_sync(0xffffffffu, s0, 1);
        s0 += __shfl_xor_sync(0xffffffffu, s0, 2);
        s1 += __shfl_xor_sync(0xffffffffu, s1, 1);
        s1 += __shfl_xor_sync(0xffffffffu, s1, 2);
        lr0 = lr0 * al0 + s0;
        lr1 = lr1 * al1 + s1;

#pragma unroll
        for (int nf = 0; nf < 16; nf++) {
            ctx[nf][0] *= al0; ctx[nf][1] *= al0;
            ctx[nf][2] *= al1; ctx[nf][3] *= al1;
        }
        // ---- PV: pH · vH ----
#pragma unroll
        for (int kk2 = 0; kk2 < 4; kk2++) {
#pragma unroll
            for (int np = 0; np < 8; np++) {
                uint4 vH2 = *(const uint4*)(stV + (kk2 * 256 + np * 32 + lane) * 16);
                const unsigned* vh = (const unsigned*)&vH2;
                mma_f16(ctx[2*np],     pH[kk2], vh);
                mma_f16(ctx[2*np + 1], pH[kk2], vh + 2);
            }
        }
        __syncthreads();
    }

    // ---- fused epilogue: stage ctx f32 in smem, emit fp16 A-pack ----
    float* cs = (float*)sm;                    // 128x132 f32 = 67584 B
    {
        float il0 = 1.0f / lr0;
        float il1 = 1.0f / lr1;
        int rl0 = m0 + g;
#pragma unroll
        for (int nf = 0; nf < 16; nf++) {
            int d = nf * 8 + 2 * t;
            *(float2*)(cs + rl0 * 132 + d) =
                make_float2(ctx[nf][0] * il0, ctx[nf][1] * il0);
            *(float2*)(cs + (rl0 + 8) * 132 + d) =
                make_float2(ctx[nf][2] * il1, ctx[nf][3] * il1);
        }
    }
    __syncthreads();

    {
        const int mtile = (b * S_ + qbase) >> 7;
        for (int it = tid; it < 2048; it += 256) {
            int w = it & 1023, kc = it >> 10;
            int ln = w & 31, rf = (w >> 5) & 7, kk = w >> 8;
            int rl = rf * 16 + (ln >> 2);
            int cl = kc * 64 + kk * 16 + 2 * (ln & 3);
            uint4 o = make_uint4(
                pack_h2(cs[rl * 132 + cl],           cs[rl * 132 + cl + 1]),
                pack_h2(cs[(rl + 8) * 132 + cl],     cs[(rl + 8) * 132 + cl + 1]),
                pack_h2(cs[rl * 132 + cl + 8],       cs[rl * 132 + cl + 9]),
                pack_h2(cs[(rl + 8) * 132 + cl + 8], cs[(rl + 8) * 132 + cl + 9]));
            size_t idx = ((size_t)(mtile * 32 + h * 2 + kc)) * 1024 +
                         (kk << 8) + (rf << 5) + ln;
            ((uint4*)g_Ctp)[idx] = o;
        }
    }
}

// ============================================================
// launch
// ============================================================
extern "C" void kernel_launch(void* const* d_in, const int* in_sizes, int n_in,
                              void* d_out, int out_size)
{
    (void)in_sizes; (void)n_in; (void)out_size;
    const float* hidden = (const float*)d_in[0];
    const float* Wq = (const float*)d_in[1];
    const float* bq = (const float*)d_in[2];
    const float* Wk = (const float*)d_in[3];
    const float* bk = (const float*)d_in[4];
    const float* Wv = (const float*)d_in[5];
    const float* bv = (const float*)d_in[6];
    const float* Wo = (const float*)d_in[7];
    float* out = (float*)d_out;

    unsigned *xp, *ctp, *wop;
    cudaGetSymbolAddress((void**)&xp,  g_Xp);
    cudaGetSymbolAddress((void**)&ctp, g_Ctp);
    cudaGetSymbolAddress((void**)&wop, g_Wop);

    cudaFuncSetAttribute(gemm_qkv,
        cudaFuncAttributeMaxDynamicSharedMemorySize, GEMM_SMEM);
    cudaFuncSetAttribute(gemm_v3,
        cudaFuncAttributeMaxDynamicSharedMemorySize, GEMM_SMEM);
    cudaFuncSetAttribute(flash_f16,
        cudaFuncAttributeMaxDynamicSharedMemorySize, FLASH_SMEM);

    const int NPACK = BSR_ * HID_ / 8 +
                      (2048 + 1024 + 1024 + 2048) * HID_ / 8 + S_ * 64;

    // 1: pack GEMM operands + RoPE tables (one launch)
    pack_all<<<(NPACK + 255) / 256, 256>>>(hidden, Wq, Wk, Wv, Wo);
    // 2: fused QKV projections + flash fragment epilogues
    gemm_qkv<<<1024, 256, GEMM_SMEM>>>(xp, bq, bk, bv);
    // 3: flash attention (single-pass fp16, Q in regs)  ← profiled launch? (slot 3)
    flash_f16<<<dim3(S_ / BQ, NH_, B_), 256, FLASH_SMEM>>>();
    // 4: O projection → final output
    gemm_v3<<<dim3(16, 32), 256, GEMM_SMEM>>>(ctp, wop, out, HID_);
}

// round 17
// speedup vs baseline: 2.0256x; 1.0169x over previous
#include <cuda_runtime.h>
#include <cuda_bf16.h>
#include <cuda_fp16.h>
#include <math.h>

#define B_    2
#define S_    2048
#define HID_  2048
#define NH_   16
#define NKV_  8
#define D_    128
#define G_    (NH_/NKV_)
#define BSR_  (B_*S_)          // 4096

// -------- scratch (__device__ globals; no allocations) --------
__device__ unsigned g_Qph[BSR_ * NH_ * D_ / 2];     // [rowblk32*NH_][kk8][wr8][ln32] uint4
__device__ unsigned g_Kph[BSR_ * NKV_ * D_ / 2];    // [b2][kvh8][kt32][kk8][np4][ln32] uint4
__device__ unsigned g_Vph[BSR_ * NKV_ * D_ / 2];    // [b2][kvh8][kt32][kk2 4][np8][ln32] uint4
__device__ unsigned g_Xp [BSR_ * HID_ / 2];         // A: [mtile][kc32][kk4][rf8][ln32] uint4
__device__ unsigned g_Ctp[BSR_ * NH_ * D_ / 2];
__device__ unsigned g_Wqp[HID_ * NH_ * D_ / 2];     // B: [ntile][kc32][kk4][np8][ln32] uint4
__device__ unsigned g_Wkp[HID_ * NKV_ * D_ / 2];
__device__ unsigned g_Wvp[HID_ * NKV_ * D_ / 2];
__device__ unsigned g_Wop[NH_ * D_ * HID_ / 2];
__device__ float g_cos[S_ * 64];
__device__ float g_sin[S_ * 64];

// ---------------- helpers ----------------
__device__ __forceinline__ void cp16(unsigned dst, const void* src) {
    asm volatile("cp.async.cg.shared.global [%0], [%1], 16;" :: "r"(dst), "l"(src));
}
__device__ __forceinline__ void cp_commit() { asm volatile("cp.async.commit_group;"); }
__device__ __forceinline__ void cp_wait1()  { asm volatile("cp.async.wait_group 1;"); }
__device__ __forceinline__ void cp_wait0()  { asm volatile("cp.async.wait_group 0;"); }

__device__ __forceinline__ unsigned pack_h2(float x, float y) {
    __half2 h;
    h.x = __float2half_rn(x);
    h.y = __float2half_rn(y);
    return *(unsigned*)&h;
}

__device__ __forceinline__ void mma_f16(float* d, const unsigned* a, const unsigned* b) {
    asm volatile(
        "mma.sync.aligned.m16n8k16.row.col.f32.f16.f16.f32 "
        "{%0,%1,%2,%3}, {%4,%5,%6,%7}, {%8,%9}, {%0,%1,%2,%3};\n"
        : "+f"(d[0]), "+f"(d[1]), "+f"(d[2]), "+f"(d[3])
        : "r"(a[0]), "r"(a[1]), "r"(a[2]), "r"(a[3]), "r"(b[0]), "r"(b[1]));
}

__device__ __forceinline__ float rope_elem(const float* sf, int r, int s, int c) {
    if (c < 64)
        return sf[r * 132 + c] * g_cos[s * 64 + c] - sf[r * 132 + c + 64] * g_sin[s * 64 + c];
    int i = c - 64;
    return sf[r * 132 + c] * g_cos[s * 64 + i] + sf[r * 132 + c - 64] * g_sin[s * 64 + i];
}

// ============================================================
// pack_all v2: smem-tiled, fully-coalesced.
// Blocks 0..511:    A tiles  (X)          mtile=bid>>4, kcpair=bid&15
// Blocks 512..767:  Wq B tiles            (N=2048)
// Blocks 768..895:  Wk B tiles            (N=1024)
// Blocks 896..1023: Wv B tiles            (N=1024)
// Blocks 1024..1279:Wo B tiles            (N=2048)
// Blocks 1280..1791: RoPE tables
// Tile = 128x128 f32 staged in smem (stride 132).
// ============================================================
#define PACK_SMEM (128 * 132 * 4)     // 67584

__global__ void pack_all_v2(const float* __restrict__ X,
                            const float* __restrict__ Wq, const float* __restrict__ Wk,
                            const float* __restrict__ Wv, const float* __restrict__ Wo)
{
    extern __shared__ float sf[];
    const int bid = blockIdx.x;
    const int tid = threadIdx.x;

    if (bid >= 1280) {
        int idx = (bid - 1280) * 256 + tid;
        if (idx < S_ * 64) {
            int s = idx >> 6, i = idx & 63;
            const double NEG_LOG_STEP = -0.2158673524681918;
            double freq = exp((double)i * NEG_LOG_STEP);
            double sd, cd;
            sincos((double)s * freq, &sd, &cd);
            g_cos[idx] = (float)cd;
            g_sin[idx] = (float)sd;
        }
        return;
    }

    const float* src; unsigned* dst; int N, mt, kcp; bool isA = false;
    if (bid < 512)       { isA = true; src = X;  dst = g_Xp;  N = 2048; mt = bid >> 4;          kcp = bid & 15; }
    else if (bid < 768)  { int t = bid - 512;  src = Wq; dst = g_Wqp; N = 2048; mt = t >> 4; kcp = t & 15; }
    else if (bid < 896)  { int t = bid - 768;  src = Wk; dst = g_Wkp; N = 1024; mt = t >> 4; kcp = t & 15; }
    else if (bid < 1024) { int t = bid - 896;  src = Wv; dst = g_Wvp; N = 1024; mt = t >> 4; kcp = t & 15; }
    else                 { int t = bid - 1024; src = Wo; dst = g_Wop; N = 2048; mt = t >> 4; kcp = t & 15; }

    // ---- coalesced tile load: 128 rows x 128 cols f32 ----
    if (isA) {
        // A tile: rows = m (stride 2048), cols = k
#pragma unroll
        for (int p = 0; p < 16; p++) {
            int it = tid + p * 256;          // 0..4095
            int row = it >> 5, c4 = (it & 31) << 2;
            float4 v = *(const float4*)(src + (size_t)(mt * 128 + row) * HID_ + kcp * 128 + c4);
            *(float4*)(sf + row * 132 + c4) = v;
        }
    } else {
        // B tile: rows = k (stride N), cols = n
#pragma unroll
        for (int p = 0; p < 16; p++) {
            int it = tid + p * 256;
            int crow = it >> 5, n4 = (it & 31) << 2;
            float4 v = *(const float4*)(src + (size_t)(kcp * 128 + crow) * N + mt * 128 + n4);
            *(float4*)(sf + crow * 132 + n4) = v;
        }
    }
    __syncthreads();

    // ---- emit packed fragments (2 K-chunks of 64 per tile) ----
    if (isA) {
#pragma unroll
        for (int kc = 0; kc < 2; kc++) {
            size_t chunk = (size_t)(mt * 32 + kcp * 2 + kc) * 1024;
            for (int it = tid; it < 1024; it += 256) {
                int lane = it & 31, rf = (it >> 5) & 7, kk = it >> 8;
                int rl = rf * 16 + (lane >> 2);
                int cl = kc * 64 + kk * 16 + 2 * (lane & 3);
                ((uint4*)dst)[chunk + it] = make_uint4(
                    pack_h2(sf[rl * 132 + cl],           sf[rl * 132 + cl + 1]),
                    pack_h2(sf[(rl + 8) * 132 + cl],     sf[(rl + 8) * 132 + cl + 1]),
                    pack_h2(sf[rl * 132 + cl + 8],       sf[rl * 132 + cl + 9]),
                    pack_h2(sf[(rl + 8) * 132 + cl + 8], sf[(rl + 8) * 132 + cl + 9]));
            }
        }
    } else {
#pragma unroll
        for (int kc = 0; kc < 2; kc++) {
            size_t chunk = (size_t)(mt * 32 + kcp * 2 + kc) * 1024;
            for (int it = tid; it < 1024; it += 256) {
                int lane = it & 31, np = (it >> 5) & 7, kk = it >> 8;
                int n0 = 2 * np * 8 + (lane >> 2);
                int n1 = n0 + 8;
                int c  = kc * 64 + kk * 16 + 2 * (lane & 3);
                ((uint4*)dst)[chunk + it] = make_uint4(
                    pack_h2(sf[c * 132 + n0],       sf[(c + 1) * 132 + n0]),
                    pack_h2(sf[(c + 8) * 132 + n0], sf[(c + 9) * 132 + n0]),
                    pack_h2(sf[c * 132 + n1],       sf[(c + 1) * 132 + n1]),
                    pack_h2(sf[(c + 8) * 132 + n1], sf[(c + 9) * 132 + n1]));
            }
        }
    }
}

// ============================================================
// FP16 GEMM core (validated R16): K-chunk 64, 3-stage cp.async,
// paired-B LDS.128.
// ============================================================
#define CHUNK_BYTES 16384
#define STAGE_BYTES (2 * CHUNK_BYTES)
#define GEMM_SMEM   (3 * STAGE_BYTES)           // 98304

__device__ __forceinline__ void gemm_issue_h(
    unsigned sbase, int stage, const unsigned* __restrict__ Ac,
    const unsigned* __restrict__ Bc, int tid)
{
    unsigned st = sbase + stage * STAGE_BYTES;
#pragma unroll
    for (int p = 0; p < 4; p++) {
        int id = tid + p * 256;
        cp16(st + id * 16,               Ac + id * 4);
        cp16(st + CHUNK_BYTES + id * 16, Bc + id * 4);
    }
    cp_commit();
}

__device__ __forceinline__ void gemm_compute_h(
    const char* st, float acc[4][4][4], int lane, int wm, int wn)
{
    const char* sA = st;
    const char* sB = st + CHUNK_BYTES;
#pragma unroll
    for (int kk = 0; kk < 4; kk++) {
        uint4 a[4];
#pragma unroll
        for (int mf = 0; mf < 4; mf++)
            a[mf] = *(const uint4*)(sA + (((kk * 8 + wm * 4 + mf) * 32) + lane) * 16);
        uint4 b2[2];
#pragma unroll
        for (int p = 0; p < 2; p++)
            b2[p] = *(const uint4*)(sB + (((kk * 8 + wn * 2 + p) * 32) + lane) * 16);
#pragma unroll
        for (int mf = 0; mf < 4; mf++) {
#pragma unroll
            for (int p = 0; p < 2; p++) {
                const unsigned* bp = (const unsigned*)&b2[p];
                mma_f16(acc[mf][2 * p],     (const unsigned*)&a[mf], bp);
                mma_f16(acc[mf][2 * p + 1], (const unsigned*)&a[mf], bp + 2);
            }
        }
    }
}

__device__ __forceinline__ void gemm_main_h(
    const unsigned* __restrict__ Ab, const unsigned* __restrict__ Bb,
    float acc[4][4][4], char* smem)
{
    const int tid  = threadIdx.x;
    const int lane = tid & 31;
    const int wm   = (tid >> 5) >> 2;
    const int wn   = (tid >> 5) & 3;
    unsigned sbase = (unsigned)__cvta_generic_to_shared(smem);

    gemm_issue_h(sbase, 0, Ab, Bb, tid);
    gemm_issue_h(sbase, 1, Ab + 4096, Bb + 4096, tid);

    for (int i = 0; i < 32; i++) {
        if (i < 31) cp_wait1(); else cp_wait0();
        __syncthreads();
        if (i + 2 < 32)
            gemm_issue_h(sbase, (i + 2) % 3,
                         Ab + (size_t)(i + 2) * 4096,
                         Bb + (size_t)(i + 2) * 4096, tid);
        gemm_compute_h(smem + (i % 3) * STAGE_BYTES, acc, lane, wm, wn);
    }
}

// ============================================================
// Fused QKV projections (validated R16)
// ============================================================
__global__ __launch_bounds__(256, 2) void gemm_qkv(
    const unsigned* __restrict__ Ap,
    const float* __restrict__ bq, const float* __restrict__ bk,
    const float* __restrict__ bv)
{
    extern __shared__ char smem[];
    float* sf = (float*)smem;
    const int id = blockIdx.x;
    const unsigned* Bp; const float* bias;
    int bx, by, mode;
    if (id < 512)      { Bp = g_Wqp; bias = bq; bx = id & 15; by = id >> 4; mode = 0; }
    else if (id < 768) { int t = id - 512; Bp = g_Wkp; bias = bk; bx = t & 7; by = t >> 3; mode = 1; }
    else               { int t = id - 768; Bp = g_Wvp; bias = bv; bx = t & 7; by = t >> 3; mode = 2; }

    float acc[4][4][4];
#pragma unroll
    for (int i = 0; i < 4; i++)
#pragma unroll
        for (int j = 0; j < 4; j++)
#pragma unroll
            for (int e = 0; e < 4; e++) acc[i][j][e] = 0.0f;

    gemm_main_h(Ap + (size_t)by * 32 * 4096, Bp + (size_t)bx * 32 * 4096, acc, smem);
    __syncthreads();

    const int tid  = threadIdx.x;
    const int lane = tid & 31;
    const int warp = tid >> 5;
    const int wm = warp >> 2, wn = warp & 3;

#pragma unroll
    for (int mf = 0; mf < 4; mf++) {
        int r = wm * 64 + mf * 16 + (lane >> 2);
#pragma unroll
        for (int nf = 0; nf < 4; nf++) {
            int col = wn * 32 + nf * 8 + 2 * (lane & 3);
            float b0 = bias[bx * 128 + col], b1 = bias[bx * 128 + col + 1];
            float v00 = acc[mf][nf][0] + b0, v01 = acc[mf][nf][1] + b1;
            float v10 = acc[mf][nf][2] + b0, v11 = acc[mf][nf][3] + b1;
            if (mode != 2) {
                *(float2*)(sf + r * 132 + col)       = make_float2(v00, v01);
                *(float2*)(sf + (r + 8) * 132 + col) = make_float2(v10, v11);
            } else {
                sf[col * 132 + r]           = v00;
                sf[(col + 1) * 132 + r]     = v01;
                sf[col * 132 + r + 8]       = v10;
                sf[(col + 1) * 132 + r + 8] = v11;
            }
        }
    }
    __syncthreads();

    if (mode == 0) {
        unsigned* Qh = g_Qph + (size_t)(by * 16 + bx) * 8192;
        for (int it = tid; it < 2048; it += 256) {
            int kk = it >> 8, wr = (it >> 5) & 7, ln = it & 31;
            int r = wr * 16 + (ln >> 2);
            int c = kk * 16 + 2 * (ln & 3);
            int s  = (by * 128 + r) & (S_ - 1);
            int s8 = s + 8;
            ((uint4*)Qh)[it] = make_uint4(
                pack_h2(rope_elem(sf, r, s, c),          rope_elem(sf, r, s, c + 1)),
                pack_h2(rope_elem(sf, r + 8, s8, c),     rope_elem(sf, r + 8, s8, c + 1)),
                pack_h2(rope_elem(sf, r, s, c + 8),      rope_elem(sf, r, s, c + 9)),
                pack_h2(rope_elem(sf, r + 8, s8, c + 8), rope_elem(sf, r + 8, s8, c + 9)));
        }
    } else if (mode == 1) {
        const int bb  = (by * 128) >> 11;
        const int kt0 = ((by * 128) & (S_ - 1)) >> 6;
        size_t kbase4 = ((size_t)((bb * NKV_ + bx) * 32 + kt0)) * 1024;
        for (int it = tid; it < 2048; it += 256) {
            int kt = it >> 10, w = it & 1023;
            int kk = w >> 7, np = (w >> 5) & 3, ln = w & 31;
            int c = kk * 16 + 2 * (ln & 3);
            unsigned hv[4];
#pragma unroll
            for (int p = 0; p < 2; p++) {
                int n = (2 * np + p) * 8 + (ln >> 2);
                int r = kt * 64 + n;
                int s = (by * 128 + r) & (S_ - 1);
                hv[2*p]   = pack_h2(rope_elem(sf, r, s, c),     rope_elem(sf, r, s, c + 1));
                hv[2*p+1] = pack_h2(rope_elem(sf, r, s, c + 8), rope_elem(sf, r, s, c + 9));
            }
            ((uint4*)g_Kph)[kbase4 + kt * 1024 + w] = make_uint4(hv[0], hv[1], hv[2], hv[3]);
        }
    } else {
        const int bb  = (by * 128) >> 11;
        const int kt0 = ((by * 128) & (S_ - 1)) >> 6;
        size_t vbase4 = ((size_t)((bb * NKV_ + bx) * 32 + kt0)) * 1024;
        for (int it = tid; it < 2048; it += 256) {
            int kt = it >> 10, w = it & 1023;
            int kk2 = w >> 8, np = (w >> 5) & 7, ln = w & 31;
            int cl = kk2 * 16 + 2 * (ln & 3);
            int r  = kt * 64 + cl;
            unsigned hv[4];
#pragma unroll
            for (int p = 0; p < 2; p++) {
                int n = (2 * np + p) * 8 + (ln >> 2);
                hv[2*p]   = pack_h2(sf[n * 132 + r],     sf[n * 132 + r + 1]);
                hv[2*p+1] = pack_h2(sf[n * 132 + r + 8], sf[n * 132 + r + 9]);
            }
            ((uint4*)g_Vph)[vbase4 + kt * 1024 + w] = make_uint4(hv[0], hv[1], hv[2], hv[3]);
        }
    }
}

// ============================================================
// O projection GEMM (validated R16)
// ============================================================
__global__ __launch_bounds__(256, 2) void gemm_v3(
    const unsigned* __restrict__ Ap, const unsigned* __restrict__ Bp,
    float* __restrict__ C, int N)
{
    extern __shared__ char smem[];
    float acc[4][4][4];
#pragma unroll
    for (int i = 0; i < 4; i++)
#pragma unroll
        for (int j = 0; j < 4; j++)
#pragma unroll
            for (int e = 0; e < 4; e++) acc[i][j][e] = 0.0f;

    gemm_main_h(Ap + (size_t)blockIdx.y * 32 * 4096,
                Bp + (size_t)blockIdx.x * 32 * 4096, acc, smem);

    const int lane = threadIdx.x & 31;
    const int warp = threadIdx.x >> 5;
    const int wm = warp >> 2, wn = warp & 3;
#pragma unroll
    for (int mf = 0; mf < 4; mf++) {
        int row = blockIdx.y * 128 + wm * 64 + mf * 16 + (lane >> 2);
#pragma unroll
        for (int nf = 0; nf < 4; nf++) {
            int col = blockIdx.x * 128 + wn * 32 + nf * 8 + 2 * (lane & 3);
            *(float2*)&C[(size_t)row * N + col] =
                make_float2(acc[mf][nf][0], acc[mf][nf][1]);
            *(float2*)&C[(size_t)(row + 8) * N + col] =
                make_float2(acc[mf][nf][2], acc[mf][nf][3]);
        }
    }
}

// ============================================================
// Flash attention (validated R16): single-pass fp16, Q in regs,
// K/V double-buffered, fp16 A-pack ctx epilogue.
// ============================================================
#define BQ 128
#define FSTAGE 32768
#define FLASH_SMEM 67584

__device__ __forceinline__ void flash_issue(
    unsigned sbase, int stage, size_t base_u, int tid)
{
    unsigned st = sbase + stage * FSTAGE;
#pragma unroll
    for (int p = 0; p < 4; p++) {
        int id = tid + p * 256;
        cp16(st + id * 16,         g_Kph + base_u + id * 4);
        cp16(st + 16384 + id * 16, g_Vph + base_u + id * 4);
    }
    cp_commit();
}

__global__ __launch_bounds__(256, 1) void flash_f16()
{
    extern __shared__ char sm[];
    const int tid  = threadIdx.x;
    const int lane = tid & 31;
    const int warp = tid >> 5;
    const int qtile = (gridDim.x - 1) - blockIdx.x;
    const int h    = blockIdx.y;
    const int b    = blockIdx.z;
    const int kvh  = h / G_;
    const int qbase = qtile * BQ;
    const float scale = 0.08838834764831845f;
    const int g = lane >> 2;
    const int t = lane & 3;
    const int m0 = warp * 16;
    unsigned sbase = (unsigned)__cvta_generic_to_shared(sm);

    const size_t kvstep = 4096;
    const size_t kvb0 = ((size_t)(b * NKV_ + kvh) * 32) * kvstep;

    flash_issue(sbase, 0, kvb0, tid);

    uint4 aQ[8];
    {
        const int mq = (b * S_ + qbase) >> 7;
        const uint4* qh = (const uint4*)g_Qph + (size_t)(mq * 16 + h) * 2048;
#pragma unroll
        for (int kk = 0; kk < 8; kk++)
            aQ[kk] = qh[kk * 256 + warp * 32 + lane];
    }

    float ctx[16][4];
#pragma unroll
    for (int i = 0; i < 16; i++)
#pragma unroll
        for (int e = 0; e < 4; e++) ctx[i][e] = 0.0f;
    float mr0 = -INFINITY, mr1 = -INFINITY, lr0 = 0.0f, lr1 = 0.0f;

    const int row0 = qbase + m0 + g;
    const int row1 = row0 + 8;
    const int ntile = 2 * qtile + 2;

    for (int j = 0; j < ntile; j++) {
        const int kb = j * 64;
        if (j + 1 < ntile) {
            flash_issue(sbase, (j + 1) & 1, kvb0 + (size_t)(j + 1) * kvstep, tid);
            cp_wait1();
        } else {
            cp_wait0();
        }
        __syncthreads();

        const char* stg = sm + (j & 1) * FSTAGE;
        const char* stK = stg;
        const char* stV = stg + 16384;

        float acc[8][4];
#pragma unroll
        for (int nf = 0; nf < 8; nf++)
#pragma unroll
            for (int e = 0; e < 4; e++) acc[nf][e] = 0.0f;

#pragma unroll
        for (int kk = 0; kk < 8; kk++) {
#pragma unroll
            for (int np = 0; np < 4; np++) {
                uint4 bH2 = *(const uint4*)(stK + (kk * 128 + np * 32 + lane) * 16);
                const unsigned* bh = (const unsigned*)&bH2;
                mma_f16(acc[2*np],     (const unsigned*)&aQ[kk], bh);
                mma_f16(acc[2*np + 1], (const unsigned*)&aQ[kk], bh + 2);
            }
        }

#pragma unroll
        for (int nf = 0; nf < 8; nf++)
#pragma unroll
            for (int e = 0; e < 4; e++) acc[nf][e] *= scale;

        if (kb + 63 > qbase + m0) {
#pragma unroll
            for (int nf = 0; nf < 8; nf++) {
                int k0 = kb + nf * 8 + 2 * t;
                if (k0     > row0) acc[nf][0] = -INFINITY;
                if (k0 + 1 > row0) acc[nf][1] = -INFINITY;
                if (k0     > row1) acc[nf][2] = -INFINITY;
                if (k0 + 1 > row1) acc[nf][3] = -INFINITY;
            }
        }

        float mx0 = -INFINITY, mx1 = -INFINITY;
#pragma unroll
        for (int nf = 0; nf < 8; nf++) {
            mx0 = fmaxf(mx0, fmaxf(acc[nf][0], acc[nf][1]));
            mx1 = fmaxf(mx1, fmaxf(acc[nf][2], acc[nf][3]));
        }
        mx0 = fmaxf(mx0, __shfl_xor_sync(0xffffffffu, mx0, 1));
        mx0 = fmaxf(mx0, __shfl_xor_sync(0xffffffffu, mx0, 2));
        mx1 = fmaxf(mx1, __shfl_xor_sync(0xffffffffu, mx1, 1));
        mx1 = fmaxf(mx1, __shfl_xor_sync(0xffffffffu, mx1, 2));

        float mn0 = fmaxf(mr0, mx0);
        float mn1 = fmaxf(mr1, mx1);
        float al0 = __expf(mr0 - mn0);
        float al1 = __expf(mr1 - mn1);
        mr0 = mn0; mr1 = mn1;

        unsigned pH[4][4];
        float s0 = 0.0f, s1 = 0.0f;
#pragma unroll
        for (int nf = 0; nf < 8; nf++) {
            float p00 = __expf(acc[nf][0] - mn0);
            float p01 = __expf(acc[nf][1] - mn0);
            float p10 = __expf(acc[nf][2] - mn1);
            float p11 = __expf(acc[nf][3] - mn1);
            s0 += p00 + p01;
            s1 += p10 + p11;
            int kk2 = nf >> 1;
            int sl  = (nf & 1) << 1;
            pH[kk2][sl]     = pack_h2(p00, p01);
            pH[kk2][sl + 1] = pack_h2(p10, p11);
        }
        s0 += __shfl_xor_sync(0xffffffffu, s0, 1);
        s0 += __shfl_xor_sync(0xffffffffu, s0, 2);
        s1 += __shfl_xor_sync(0xffffffffu, s1, 1);
        s1 += __shfl_xor_sync(0xffffffffu, s1, 2);
        lr0 = lr0 * al0 + s0;
        lr1 = lr1 * al1 + s1;

#pragma unroll
        for (int nf = 0; nf < 16; nf++) {
            ctx[nf][0] *= al0; ctx[nf][1] *= al0;
            ctx[nf][2] *= al1; ctx[nf][3] *= al1;
        }
#pragma unroll
        for (int kk2 = 0; kk2 < 4; kk2++) {
#pragma unroll
            for (int np = 0; np < 8; np++) {
                uint4 vH2 = *(const uint4*)(stV + (kk2 * 256 + np * 32 + lane) * 16);
                const unsigned* vh = (const unsigned*)&vH2;
                mma_f16(ctx[2*np],     pH[kk2], vh);
                mma_f16(ctx[2*np + 1], pH[kk2], vh + 2);
            }
        }
        __syncthreads();
    }

    // ---- fused epilogue: stage ctx f32 in smem, emit fp16 A-pack ----
    float* cs = (float*)sm;
    {
        float il0 = 1.0f / lr0;
        float il1 = 1.0f / lr1;
        int rl0 = m0 + g;
#pragma unroll
        for (int nf = 0; nf < 16; nf++) {
            int d = nf * 8 + 2 * t;
            *(float2*)(cs + rl0 * 132 + d) =
                make_float2(ctx[nf][0] * il0, ctx[nf][1] * il0);
            *(float2*)(cs + (rl0 + 8) * 132 + d) =
                make_float2(ctx[nf][2] * il1, ctx[nf][3] * il1);
        }
    }
    __syncthreads();

    {
        const int mtile = (b * S_ + qbase) >> 7;
        for (int it = tid; it < 2048; it += 256) {
            int w = it & 1023, kc = it >> 10;
            int ln = w & 31, rf = (w >> 5) & 7, kk = w >> 8;
            int rl = rf * 16 + (ln >> 2);
            int cl = kc * 64 + kk * 16 + 2 * (ln & 3);
            uint4 o = make_uint4(
                pack_h2(cs[rl * 132 + cl],           cs[rl * 132 + cl + 1]),
                pack_h2(cs[(rl + 8) * 132 + cl],     cs[(rl + 8) * 132 + cl + 1]),
                pack_h2(cs[rl * 132 + cl + 8],       cs[rl * 132 + cl + 9]),
                pack_h2(cs[(rl + 8) * 132 + cl + 8], cs[(rl + 8) * 132 + cl + 9]));
            size_t idx = ((size_t)(mtile * 32 + h * 2 + kc)) * 1024 +
                         (kk << 8) + (rf << 5) + ln;
            ((uint4*)g_Ctp)[idx] = o;
        }
    }
}

// ============================================================
// launch
// ============================================================
extern "C" void kernel_launch(void* const* d_in, const int* in_sizes, int n_in,
                              void* d_out, int out_size)
{
    (void)in_sizes; (void)n_in; (void)out_size;
    const float* hidden = (const float*)d_in[0];
    const float* Wq = (const float*)d_in[1];
    const float* bq = (const float*)d_in[2];
    const float* Wk = (const float*)d_in[3];
    const float* bk = (const float*)d_in[4];
    const float* Wv = (const float*)d_in[5];
    const float* bv = (const float*)d_in[6];
    const float* Wo = (const float*)d_in[7];
    float* out = (float*)d_out;

    unsigned *xp, *ctp, *wop;
    cudaGetSymbolAddress((void**)&xp,  g_Xp);
    cudaGetSymbolAddress((void**)&ctp, g_Ctp);
    cudaGetSymbolAddress((void**)&wop, g_Wop);

    cudaFuncSetAttribute(pack_all_v2,
        cudaFuncAttributeMaxDynamicSharedMemorySize, PACK_SMEM);
    cudaFuncSetAttribute(gemm_qkv,
        cudaFuncAttributeMaxDynamicSharedMemorySize, GEMM_SMEM);
    cudaFuncSetAttribute(gemm_v3,
        cudaFuncAttributeMaxDynamicSharedMemorySize, GEMM_SMEM);
    cudaFuncSetAttribute(flash_f16,
        cudaFuncAttributeMaxDynamicSharedMemorySize, FLASH_SMEM);

    // 1: pack GEMM operands (smem-tiled, coalesced) + RoPE tables
    pack_all_v2<<<1792, 256, PACK_SMEM>>>(hidden, Wq, Wk, Wv, Wo);
    // 2: fused QKV projections + flash fragment epilogues
    gemm_qkv<<<1024, 256, GEMM_SMEM>>>(xp, bq, bk, bv);
    // 3: flash attention (single-pass fp16, Q in regs)
    flash_f16<<<dim3(S_ / BQ, NH_, B_), 256, FLASH_SMEM>>>();
    // 4: O projection → final output
    gemm_v3<<<dim3(16, 32), 256, GEMM_SMEM>>>(ctp, wop, out, HID_);
}